// round 10
// baseline (speedup 1.0000x reference)
#include <cuda_runtime.h>
#include <cstdint>
#include <cstddef>

#define NN   20000
#define EE   320000
#define HH   8
#define FUNI 256
#define FOUT 64
#define HF   512   // H*FOUT

// ---------------- scratch (device globals; no runtime allocation) ----------------
// All GEMM activations/weights live as packed bf16x2 (uint32).
__device__ uint32_t g_trans0[NN * FUNI / 2];
__device__ uint32_t g_trans1[NN * FUNI / 2];
__device__ uint32_t g_Bp[512 * 256];        // repacked GAT weight, [N][K/2] bf16x2
__device__ uint32_t g_hp[NN * HF / 2];      // projected features (bf16); also packed hemb1 early
__device__ uint32_t g_x0[NN * HF / 2];      // layer-0 aggregated output (bf16, ELU'd); also packed hemb0 early
__device__ float g_o1a[NN * HF];            // layer-1 aggregated output, type 0 (fp32)
__device__ float g_o1b[NN * HF];            // layer-1 aggregated output, type 1 (fp32)
__device__ float g_s[NN * HH];
__device__ float g_t[NN * HH];
__device__ float g_fa[FOUT];

// CSR scratch
__device__ int g_cnt[NN];
__device__ int g_rowptr[2][NN + 1];
__device__ int g_woff[NN];
__device__ int g_csr[2][EE];

// ---------------- helpers ----------------
__device__ __forceinline__ uint32_t smem_to_u32(const void* p) {
    uint32_t a;
    asm("{ .reg .u64 t; cvta.to.shared.u64 t, %1; cvt.u32.u64 %0, t; }" : "=r"(a) : "l"(p));
    return a;
}
__device__ __forceinline__ void cp16(uint32_t saddr, const void* g) {
    asm volatile("cp.async.cg.shared.global [%0], [%1], 16;" :: "r"(saddr), "l"(g));
}
__device__ __forceinline__ void sts_zero16(uint32_t saddr) {
    asm volatile("st.shared.v4.b32 [%0], {%1,%1,%1,%1};" :: "r"(saddr), "r"(0u));
}
#define CP_COMMIT() asm volatile("cp.async.commit_group;" ::: "memory")
#define CP_WAIT2()  asm volatile("cp.async.wait_group 2;" ::: "memory")

// pack two fp32 -> bf16x2 (lo = a, hi = b), round-to-nearest
__device__ __forceinline__ uint32_t pack_bf16x2(float a, float b) {
    uint32_t r;
    asm("cvt.rn.bf16x2.f32 %0, %1, %2;" : "=r"(r) : "f"(b), "f"(a));
    return r;
}
// unpack bf16x2 -> fp32 (exact)
__device__ __forceinline__ float bf_lo(uint32_t u) { return __uint_as_float(u << 16); }
__device__ __forceinline__ float bf_hi(uint32_t u) { return __uint_as_float(u & 0xffff0000u); }

__device__ __forceinline__ float eluf(float x) { return x > 0.f ? x : (__expf(x) - 1.f); }

__device__ __forceinline__ void mma_bf16(float* c, const uint32_t* a, const uint32_t* b) {
    asm volatile("mma.sync.aligned.m16n8k16.row.col.f32.bf16.bf16.f32 "
                 "{%0,%1,%2,%3}, {%4,%5,%6,%7}, {%8,%9}, {%0,%1,%2,%3};"
                 : "+f"(c[0]), "+f"(c[1]), "+f"(c[2]), "+f"(c[3])
                 : "r"(a[0]), "r"(a[1]), "r"(a[2]), "r"(a[3]), "r"(b[0]), "r"(b[1]));
}

// ---------------- bf16 mma GEMM: C[M,NC] = A[M,K] @ Bt[NC,K]^T (all bf16x2-packed) ----------------
// Block tile 128x128, 8 warps (4x2), warp tile 32x64 (2x8 m16n8k16 atoms).
// K-chunks of 32 bf16 (16 u32 per row), 3-stage cp.async pipeline,
// SMEM row stride 20 u32 (16 data + 4 pad, conflict-free for the g/t fragment pattern).
#define STAGES  3
#define STRIDEU 20
#define TILEU   (128 * STRIDEU)            // u32 per tile
#define STAGEU  (2 * TILEU)
#define SMEM_GEMM (STAGES * STAGEU * 4)    // 61440 bytes

__global__ __launch_bounds__(256, 2)
void gemm_bf16(const uint32_t* __restrict__ A, const uint32_t* __restrict__ Bt,
               uint32_t* __restrict__ C, int M, int K, int NC)
{
    extern __shared__ uint32_t smu[];
    const int tid  = threadIdx.x;
    const int wid  = tid >> 5, lane = tid & 31;
    const int g    = lane >> 2, t = lane & 3;
    const int bm   = blockIdx.y << 7, bn = blockIdx.x << 7;
    const int m0   = (wid >> 1) * 32;
    const int n0   = (wid & 1) * 64;
    const int KU   = K >> 1;               // u32 per row
    const int NCU  = NC >> 1;
    const int P    = K >> 5;               // chunks of 32 bf16

    const uint32_t sb = smem_to_u32(smu);
    const int lrow = tid >> 2;              // 0..63 (+64 for j=1)
    const int lc4  = tid & 3;               // 16B chunk within 64B row

    float acc[2][8][4];
#pragma unroll
    for (int i = 0; i < 2; i++)
#pragma unroll
        for (int j = 0; j < 8; j++)
#pragma unroll
            for (int q = 0; q < 4; q++) acc[i][j][q] = 0.f;

#pragma unroll
    for (int s = 0; s < STAGES; s++) {
        uint32_t stb = sb + s * STAGEU * 4;
#pragma unroll
        for (int j = 0; j < 2; j++) {
            int row = lrow + j * 64;
            uint32_t sa = stb + (row * STRIDEU + lc4 * 4) * 4;
            int ar = bm + row;
            if (ar < M) cp16(sa, A + (size_t)ar * KU + s * 16 + lc4 * 4);
            else        sts_zero16(sa);
            uint32_t sbB = stb + TILEU * 4 + (row * STRIDEU + lc4 * 4) * 4;
            cp16(sbB, Bt + (size_t)(bn + row) * KU + s * 16 + lc4 * 4);
        }
        CP_COMMIT();
    }

    for (int p = 0; p < P; p++) {
        const int slot = p % STAGES;
        CP_WAIT2();
        __syncthreads();
        const uint32_t* As = smu + slot * STAGEU;
        const uint32_t* Bs = As + TILEU;

#pragma unroll
        for (int ks = 0; ks < 2; ks++) {
            uint32_t a[2][4], b[8][2];
#pragma unroll
            for (int i = 0; i < 2; i++) {
                int base = (m0 + i * 16 + g) * STRIDEU + ks * 8 + t;
                a[i][0] = As[base];
                a[i][1] = As[base + 8 * STRIDEU];
                a[i][2] = As[base + 4];
                a[i][3] = As[base + 8 * STRIDEU + 4];
            }
#pragma unroll
            for (int j = 0; j < 8; j++) {
                int bb = (n0 + j * 8 + g) * STRIDEU + ks * 8 + t;
                b[j][0] = Bs[bb];
                b[j][1] = Bs[bb + 4];
            }
#pragma unroll
            for (int i = 0; i < 2; i++)
#pragma unroll
                for (int j = 0; j < 8; j++)
                    mma_bf16(acc[i][j], a[i], b[j]);
        }
        __syncthreads();

        int np = p + STAGES;
        if (np < P) {
            uint32_t stb = sb + slot * STAGEU * 4;
#pragma unroll
            for (int j = 0; j < 2; j++) {
                int row = lrow + j * 64;
                uint32_t sa = stb + (row * STRIDEU + lc4 * 4) * 4;
                int ar = bm + row;
                if (ar < M) cp16(sa, A + (size_t)ar * KU + np * 16 + lc4 * 4);
                else        sts_zero16(sa);
                uint32_t sbB = stb + TILEU * 4 + (row * STRIDEU + lc4 * 4) * 4;
                cp16(sbB, Bt + (size_t)(bn + row) * KU + np * 16 + lc4 * 4);
            }
        }
        CP_COMMIT();   // empty groups at tail keep wait_group accounting uniform
    }

    // ---- epilogue: pack fp32 accumulators to bf16x2 ----
#pragma unroll
    for (int i = 0; i < 2; i++) {
        int r0 = bm + m0 + i * 16 + g;
#pragma unroll
        for (int j = 0; j < 8; j++) {
            int colu = ((bn + n0 + j * 8) >> 1) + t;   // u32 column
            if (r0 < M)
                C[(size_t)r0 * NCU + colu] = pack_bf16x2(acc[i][j][0], acc[i][j][1]);
            if (r0 + 8 < M)
                C[(size_t)(r0 + 8) * NCU + colu] = pack_bf16x2(acc[i][j][2], acc[i][j][3]);
        }
    }
}

// ---------------- CSR build ----------------
__global__ void zero_cnt() {
    int i = blockIdx.x * blockDim.x + threadIdx.x;
    if (i < NN) g_cnt[i] = 0;
}
__global__ void hist_kernel(const int* __restrict__ trg) {
    int e = blockIdx.x * blockDim.x + threadIdx.x;
    if (e < EE) atomicAdd(&g_cnt[trg[e]], 1);
}
#define SCAN_CH 20
__global__ __launch_bounds__(1024) void scan_kernel(int t) {
    __shared__ int part[1024];
    int tid = threadIdx.x;
    int base = tid * SCAN_CH;
    int loc[SCAN_CH];
    int s = 0;
#pragma unroll
    for (int i = 0; i < SCAN_CH; i++) {
        int idx = base + i;
        int v = (idx < NN) ? g_cnt[idx] : 0;
        loc[i] = s;
        s += v;
    }
    part[tid] = s;
    __syncthreads();
    for (int d = 1; d < 1024; d <<= 1) {
        int v = (tid >= d) ? part[tid - d] : 0;
        __syncthreads();
        part[tid] += v;
        __syncthreads();
    }
    int excl = part[tid] - s;
#pragma unroll
    for (int i = 0; i < SCAN_CH; i++) {
        int idx = base + i;
        if (idx < NN) {
            int v = loc[i] + excl;
            g_rowptr[t][idx] = v;
            g_woff[idx] = v;
        }
    }
    if (tid == 1023) g_rowptr[t][NN] = part[1023];
}
__global__ void fill_kernel(const int* __restrict__ src, const int* __restrict__ trg, int t) {
    int e = blockIdx.x * blockDim.x + threadIdx.x;
    if (e >= EE) return;
    int p = atomicAdd(&g_woff[trg[e]], 1);
    g_csr[t][p] = src[e];
}

// ---------------- s/t projections (hp is bf16-packed) ----------------
__global__ void st_kernel(const uint32_t* __restrict__ hp,
                          const float* __restrict__ asrc,
                          const float* __restrict__ atrg) {
    int idx = blockIdx.x * blockDim.x + threadIdx.x;
    if (idx >= NN * HH) return;
    int h = idx & 7;
    const uint4* v = (const uint4*)(hp + (size_t)idx * 32);   // 8 uint4 = 64 bf16
    const float4* a = (const float4*)(asrc + h * 64);
    const float4* b = (const float4*)(atrg + h * 64);
    float s = 0.f, t = 0.f;
#pragma unroll
    for (int q = 0; q < 8; q++) {
        uint4 pk = v[q];
        float4 a0 = a[2 * q], a1 = a[2 * q + 1];
        float4 b0 = b[2 * q], b1 = b[2 * q + 1];
        float f0 = bf_lo(pk.x), f1 = bf_hi(pk.x);
        float f2 = bf_lo(pk.y), f3 = bf_hi(pk.y);
        float f4 = bf_lo(pk.z), f5 = bf_hi(pk.z);
        float f6 = bf_lo(pk.w), f7 = bf_hi(pk.w);
        s += f0 * a0.x + f1 * a0.y + f2 * a0.z + f3 * a0.w
           + f4 * a1.x + f5 * a1.y + f6 * a1.z + f7 * a1.w;
        t += f0 * b0.x + f1 * b0.y + f2 * b0.z + f3 * b0.w
           + f4 * b1.x + f5 * b1.y + f6 * b1.z + f7 * b1.w;
    }
    g_s[idx] = s;
    g_t[idx] = t;
}

// ---------------- gather-aggregate: 2 warps per target node (4 heads each) ----------------
// mode 0: fp32 out.  mode 1: ELU + bf16-packed out.
__global__ __launch_bounds__(256) void gather_agg(const int* __restrict__ csr,
                                                  const int* __restrict__ rowptr,
                                                  const uint32_t* __restrict__ hp,
                                                  void* __restrict__ outp,
                                                  int mode)
{
    int gw = (blockIdx.x * 256 + threadIdx.x) >> 5;
    int lane = threadIdx.x & 31;
    int node = gw >> 1, half = gw & 1;
    if (node >= NN) return;
    int beg = rowptr[node], end = rowptr[node + 1];
    int c = half * 32 + lane;                      // uint4 chunk (8 bf16) within the 512-col row

    float tval = (lane < 4) ? g_t[node * 8 + half * 4 + lane] : 0.f;
    float denom = 0.f;                             // lanes 0..3: per-head denominator
    float acc[8];
#pragma unroll
    for (int k = 0; k < 8; k++) acc[k] = 0.f;

    int srcp = (beg < end) ? csr[beg] : 0;
    for (int p = beg; p < end; p++) {
        int nxt = (p + 1 < end) ? csr[p + 1] : 0;
        float ex = 0.f;
        if (lane < 4) {
            float v = g_s[srcp * 8 + half * 4 + lane] + tval;
            ex = __expf(fmaxf(v, 0.2f * v));       // global max-shift cancels in alpha
            denom += ex;
        }
        uint4 v = ((const uint4*)(hp + (size_t)srcp * 256))[c];
        float al = __shfl_sync(0xffffffffu, ex, lane >> 3);
        acc[0] += al * bf_lo(v.x); acc[1] += al * bf_hi(v.x);
        acc[2] += al * bf_lo(v.y); acc[3] += al * bf_hi(v.y);
        acc[4] += al * bf_lo(v.z); acc[5] += al * bf_hi(v.z);
        acc[6] += al * bf_lo(v.w); acc[7] += al * bf_hi(v.w);
        srcp = nxt;
    }

    float dn = __shfl_sync(0xffffffffu, denom, lane >> 3) + 1e-16f;
    float inv = 1.f / dn;
#pragma unroll
    for (int k = 0; k < 8; k++) acc[k] *= inv;

    if (mode == 0) {
        float* out = (float*)outp;
        float4* ob = (float4*)(out + (size_t)node * 512 + c * 8);
        ob[0] = make_float4(acc[0], acc[1], acc[2], acc[3]);
        ob[1] = make_float4(acc[4], acc[5], acc[6], acc[7]);
    } else {
        uint32_t* out = (uint32_t*)outp;
        uint4 pk;
        pk.x = pack_bf16x2(eluf(acc[0]), eluf(acc[1]));
        pk.y = pack_bf16x2(eluf(acc[2]), eluf(acc[3]));
        pk.z = pack_bf16x2(eluf(acc[4]), eluf(acc[5]));
        pk.w = pack_bf16x2(eluf(acc[6]), eluf(acc[7]));
        ((uint4*)(out + (size_t)node * 256))[c] = pk;
    }
}

// ---------------- prep kernels ----------------
// pack fp32 pairs -> bf16x2
__global__ void pack_bf16_k(uint32_t* __restrict__ dst, const float* __restrict__ src, int n2) {
    int i = blockIdx.x * blockDim.x + threadIdx.x;
    if (i < n2) dst[i] = pack_bf16x2(src[2 * i], src[2 * i + 1]);
}
// W [128,256] -> Wt u32 [256][64]: Wt[n][ku] = pack(W[2ku][n], W[2ku+1][n])
__global__ void transpose_pack(uint32_t* __restrict__ Wt, const float* __restrict__ W) {
    int i = blockIdx.x * blockDim.x + threadIdx.x;
    if (i >= 256 * 64) return;
    int n = i >> 6, ku = i & 63;
    Wt[i] = pack_bf16x2(W[(2 * ku) * 256 + n], W[(2 * ku + 1) * 256 + n]);
}
// w (H, fin, 64) -> Bt u32 [512][fin/2]: Bt[h*64+o][ku] = pack(w[h][2ku][o], w[h][2ku+1][o])
__global__ void repack_pack(uint32_t* __restrict__ Bt, const float* __restrict__ w, int fin) {
    int finu = fin >> 1;
    int i = blockIdx.x * blockDim.x + threadIdx.x;
    if (i >= 512 * finu) return;
    int n = i / finu, ku = i % finu;
    int h = n >> 6, o = n & 63;
    int k0 = 2 * ku;
    Bt[i] = pack_bf16x2(w[((size_t)(h * fin + k0) << 6) + o],
                        w[((size_t)(h * fin + k0 + 1) << 6) + o]);
}

__global__ void fa_kernel(const uint32_t* __restrict__ trans1, const float* __restrict__ aw1) {
    int o = threadIdx.x;
    float acc = 0.f;
    for (int f2 = 0; f2 < 128; f2++) {
        uint32_t u = trans1[f2];
        acc += bf_lo(u) * aw1[(2 * f2) * 64 + o] + bf_hi(u) * aw1[(2 * f2 + 1) * 64 + o];
    }
    g_fa[o] = acc;
}

__global__ __launch_bounds__(64) void final_kernel(const float* __restrict__ aw2,
                                                   const float* __restrict__ am,
                                                   const float* __restrict__ fcw,
                                                   const float* __restrict__ fcb,
                                                   float* __restrict__ out) {
    __shared__ float ta[2][64];
    __shared__ float r0[64], r1[64];
    __shared__ float sc[2];
    int n = blockIdx.x, o = threadIdx.x;

    float m0 = 0.f, m1 = 0.f;
    const float* p0 = g_o1a + (size_t)n * 512 + o;
    const float* p1 = g_o1b + (size_t)n * 512 + o;
#pragma unroll
    for (int h = 0; h < 8; h++) { m0 += p0[h * 64]; m1 += p1[h * 64]; }
    m0 *= 0.125f; m1 *= 0.125f;
    ta[0][o] = m0; ta[1][o] = m1;
    __syncthreads();

    float amo = am[o];
    float fa = g_fa[o];
    {
        float acc0 = fa, acc1 = fa;
        for (int d = 0; d < 64; d++) {
            float w = aw2[d * 64 + o];
            acc0 += ta[0][d] * w;
            acc1 += ta[1][d] * w;
        }
        r0[o] = tanhf(acc0) * amo;
        r1[o] = tanhf(acc1) * amo;
    }
    __syncthreads();
    if (o == 0) {
        float s0 = 0.f, s1 = 0.f;
        for (int d = 0; d < 64; d++) { s0 += r0[d]; s1 += r1[d]; }
        sc[0] = s0; sc[1] = s1;
    }
    __syncthreads();
    float mx = fmaxf(sc[0], sc[1]);
    float b0 = __expf(sc[0] - mx), b1 = __expf(sc[1] - mx);
    float inv = 1.f / (b0 + b1);
    b0 *= inv; b1 *= inv;
    float fus = b0 * m0 + b1 * m1;

    r0[o] = m0 * fcw[o * 2 + 0] + m1 * fcw[(64 + o) * 2 + 0] + fus * fcw[(128 + o) * 2 + 0];
    r1[o] = m0 * fcw[o * 2 + 1] + m1 * fcw[(64 + o) * 2 + 1] + fus * fcw[(128 + o) * 2 + 1];
    __syncthreads();
    if (o == 0) {
        float l0 = fcb[0], l1 = fcb[1];
        for (int d = 0; d < 64; d++) { l0 += r0[d]; l1 += r1[d]; }
        float m = fmaxf(l0, l1);
        float lse = m + logf(__expf(l0 - m) + __expf(l1 - m));
        out[n * 2 + 0] = l0 - lse;
        out[n * 2 + 1] = l1 - lse;
    }
}

// ---------------- launcher ----------------
extern "C" void kernel_launch(void* const* d_in, const int* in_sizes, int n_in,
                              void* d_out, int out_size)
{
    const float* hemb0 = (const float*)d_in[0];
    const float* hemb1 = (const float*)d_in[1];
    const float* W0    = (const float*)d_in[2];
    const float* W1    = (const float*)d_in[3];
    const float* gw[2][2]    = {{(const float*)d_in[4],  (const float*)d_in[7]},
                                {(const float*)d_in[10], (const float*)d_in[13]}};
    const float* gasrc[2][2] = {{(const float*)d_in[5],  (const float*)d_in[8]},
                                {(const float*)d_in[11], (const float*)d_in[14]}};
    const float* gatrg[2][2] = {{(const float*)d_in[6],  (const float*)d_in[9]},
                                {(const float*)d_in[12], (const float*)d_in[15]}};
    const float* aw1 = (const float*)d_in[16];
    const float* aw2 = (const float*)d_in[17];
    const float* am  = (const float*)d_in[18];
    const float* fcw = (const float*)d_in[19];
    const float* fcb = (const float*)d_in[20];
    const int* edge[2] = {(const int*)d_in[21], (const int*)d_in[22]};

    uint32_t *trans[2], *Bp, *hp, *x0;
    float *o1[2];
    int *csr[2], *rowptr[2];
    cudaGetSymbolAddress((void**)&trans[0], g_trans0);
    cudaGetSymbolAddress((void**)&trans[1], g_trans1);
    cudaGetSymbolAddress((void**)&Bp,  g_Bp);
    cudaGetSymbolAddress((void**)&hp,  g_hp);
    cudaGetSymbolAddress((void**)&x0,  g_x0);
    cudaGetSymbolAddress((void**)&o1[0], g_o1a);
    cudaGetSymbolAddress((void**)&o1[1], g_o1b);
    {
        int* base;
        cudaGetSymbolAddress((void**)&base, g_csr);
        csr[0] = base; csr[1] = base + EE;
        cudaGetSymbolAddress((void**)&base, g_rowptr);
        rowptr[0] = base; rowptr[1] = base + (NN + 1);
    }

    cudaFuncSetAttribute(gemm_bf16, cudaFuncAttributeMaxDynamicSharedMemorySize, SMEM_GEMM);

    const dim3 gridT(FUNI / 128, (NN + 127) / 128);
    const dim3 gridH(HF / 128,  (NN + 127) / 128);
    const int gatherBlocks = (NN * 64 + 255) / 256;   // 2 warps per node

    // CSR build (per type; reused by both layers)
    for (int t = 0; t < 2; t++) {
        const int* src = edge[t];
        const int* trg = edge[t] + EE;
        zero_cnt<<<(NN + 255) / 256, 256>>>();
        hist_kernel<<<(EE + 255) / 256, 256>>>(trg);
        scan_kernel<<<1, 1024>>>(t);
        fill_kernel<<<(EE + 255) / 256, 256>>>(src, trg, t);
    }

    // pack hemb inputs to bf16 (x0 and hp are free this early)
    pack_bf16_k<<<(NN * 64 + 255) / 256, 256>>>(x0, hemb0, NN * 64);
    pack_bf16_k<<<(NN * 64 + 255) / 256, 256>>>(hp, hemb1, NN * 64);

    // trans GEMMs
    transpose_pack<<<(256 * 64 + 255) / 256, 256>>>(Bp, W0);
    gemm_bf16<<<gridT, 256, SMEM_GEMM>>>(x0, Bp, trans[0], NN, 128, FUNI);
    transpose_pack<<<(256 * 64 + 255) / 256, 256>>>(Bp, W1);
    gemm_bf16<<<gridT, 256, SMEM_GEMM>>>(hp, Bp, trans[1], NN, 128, FUNI);

    for (int t = 0; t < 2; t++) {
        // ---- layer 0 (fin = 256); ELU + bf16 pack fused into gather ----
        repack_pack<<<(512 * 128 + 255) / 256, 256>>>(Bp, gw[t][0], FUNI);
        gemm_bf16<<<gridH, 256, SMEM_GEMM>>>(trans[t], Bp, hp, NN, FUNI, HF);
        st_kernel<<<(NN * HH + 255) / 256, 256>>>(hp, gasrc[t][0], gatrg[t][0]);
        gather_agg<<<gatherBlocks, 256>>>(csr[t], rowptr[t], hp, x0, 1);

        // ---- layer 1 (fin = 512), fp32 output for the final stage ----
        repack_pack<<<(512 * 256 + 255) / 256, 256>>>(Bp, gw[t][1], HF);
        gemm_bf16<<<gridH, 256, SMEM_GEMM>>>(x0, Bp, hp, NN, HF, HF);
        st_kernel<<<(NN * HH + 255) / 256, 256>>>(hp, gasrc[t][1], gatrg[t][1]);
        gather_agg<<<gatherBlocks, 256>>>(csr[t], rowptr[t], hp, o1[t], 0);
    }

    fa_kernel<<<1, 64>>>(trans[1], aw1);
    final_kernel<<<NN, 64>>>(aw2, am, fcw, fcb, (float*)d_out);
}

// round 11
// speedup vs baseline: 1.5147x; 1.5147x over previous
#include <cuda_runtime.h>
#include <cstdint>
#include <cstddef>

#define NN   20000
#define EE   320000
#define HH   8
#define FUNI 256
#define FOUT 64
#define HF   512   // H*FOUT

// ---------------- scratch (device globals; no runtime allocation) ----------------
// All GEMM activations/weights live as packed bf16x2 (uint32).
__device__ uint32_t g_trans0[NN * FUNI / 2];
__device__ uint32_t g_trans1[NN * FUNI / 2];
__device__ uint32_t g_Bp[512 * 256];        // repacked GAT weight, [N][K/2] bf16x2
__device__ uint32_t g_hp[NN * HF / 2];      // projected features (bf16); also packed hemb1 early
__device__ uint32_t g_x0[NN * HF / 2];      // layer-0 aggregated output (bf16, ELU'd); also packed hemb0 early
__device__ float g_o1a[NN * HF];            // layer-1 aggregated output, type 0 (fp32)
__device__ float g_o1b[NN * HF];            // layer-1 aggregated output, type 1 (fp32)
__device__ float g_s[NN * HH];
__device__ float g_t[NN * HH];
__device__ float g_fa[FOUT];

// CSR scratch
__device__ int g_cnt[NN];
__device__ int g_rowptr[2][NN + 1];
__device__ int g_woff[NN];
__device__ int g_csr[2][EE];

// ---------------- helpers ----------------
__device__ __forceinline__ uint32_t smem_to_u32(const void* p) {
    uint32_t a;
    asm("{ .reg .u64 t; cvta.to.shared.u64 t, %1; cvt.u32.u64 %0, t; }" : "=r"(a) : "l"(p));
    return a;
}
__device__ __forceinline__ void cp16(uint32_t saddr, const void* g) {
    asm volatile("cp.async.cg.shared.global [%0], [%1], 16;" :: "r"(saddr), "l"(g));
}
__device__ __forceinline__ void sts_zero16(uint32_t saddr) {
    asm volatile("st.shared.v4.b32 [%0], {%1,%1,%1,%1};" :: "r"(saddr), "r"(0u));
}
#define CP_COMMIT() asm volatile("cp.async.commit_group;" ::: "memory")
#define CP_WAIT2()  asm volatile("cp.async.wait_group 2;" ::: "memory")

// pack two fp32 -> bf16x2 (lo = a, hi = b), round-to-nearest
__device__ __forceinline__ uint32_t pack_bf16x2(float a, float b) {
    uint32_t r;
    asm("cvt.rn.bf16x2.f32 %0, %1, %2;" : "=r"(r) : "f"(b), "f"(a));
    return r;
}
// unpack bf16x2 -> fp32 (exact)
__device__ __forceinline__ float bf_lo(uint32_t u) { return __uint_as_float(u << 16); }
__device__ __forceinline__ float bf_hi(uint32_t u) { return __uint_as_float(u & 0xffff0000u); }

__device__ __forceinline__ float eluf(float x) { return x > 0.f ? x : (__expf(x) - 1.f); }

__device__ __forceinline__ void mma_bf16(float* c, const uint32_t* a, const uint32_t* b) {
    asm volatile("mma.sync.aligned.m16n8k16.row.col.f32.bf16.bf16.f32 "
                 "{%0,%1,%2,%3}, {%4,%5,%6,%7}, {%8,%9}, {%0,%1,%2,%3};"
                 : "+f"(c[0]), "+f"(c[1]), "+f"(c[2]), "+f"(c[3])
                 : "r"(a[0]), "r"(a[1]), "r"(a[2]), "r"(a[3]), "r"(b[0]), "r"(b[1]));
}

// ---------------- bf16 mma GEMM: C[M,NC] = A[M,K] @ Bt[NC,K]^T (all bf16x2-packed) ----------------
// Block tile 128x128, 8 warps (4x2), warp tile 32x64 (2x8 m16n8k16 atoms).
// K-chunks of 32 bf16 (16 u32 per row), 3-stage cp.async pipeline,
// SMEM row stride 20 u32 (16 data + 4 pad, conflict-free).
#define STAGES  3
#define STRIDEU 20
#define TILEU   (128 * STRIDEU)            // u32 per tile
#define STAGEU  (2 * TILEU)
#define SMEM_GEMM (STAGES * STAGEU * 4)    // 61440 bytes

__global__ __launch_bounds__(256, 2)
void gemm_bf16(const uint32_t* __restrict__ A, const uint32_t* __restrict__ Bt,
               uint32_t* __restrict__ C, int M, int K, int NC)
{
    extern __shared__ uint32_t smu[];
    const int tid  = threadIdx.x;
    const int wid  = tid >> 5, lane = tid & 31;
    const int g    = lane >> 2, t = lane & 3;
    const int bm   = blockIdx.y << 7, bn = blockIdx.x << 7;
    const int m0   = (wid >> 1) * 32;
    const int n0   = (wid & 1) * 64;
    const int KU   = K >> 1;               // u32 per row
    const int NCU  = NC >> 1;
    const int P    = K >> 5;               // chunks of 32 bf16

    const uint32_t sb = smem_to_u32(smu);
    const int lrow = tid >> 2;              // 0..63 (+64 for j=1)
    const int lc4  = tid & 3;

    float acc[2][8][4];
#pragma unroll
    for (int i = 0; i < 2; i++)
#pragma unroll
        for (int j = 0; j < 8; j++)
#pragma unroll
            for (int q = 0; q < 4; q++) acc[i][j][q] = 0.f;

#pragma unroll
    for (int s = 0; s < STAGES; s++) {
        uint32_t stb = sb + s * STAGEU * 4;
#pragma unroll
        for (int j = 0; j < 2; j++) {
            int row = lrow + j * 64;
            uint32_t sa = stb + (row * STRIDEU + lc4 * 4) * 4;
            int ar = bm + row;
            if (ar < M) cp16(sa, A + (size_t)ar * KU + s * 16 + lc4 * 4);
            else        sts_zero16(sa);
            uint32_t sbB = stb + TILEU * 4 + (row * STRIDEU + lc4 * 4) * 4;
            cp16(sbB, Bt + (size_t)(bn + row) * KU + s * 16 + lc4 * 4);
        }
        CP_COMMIT();
    }

    for (int p = 0; p < P; p++) {
        const int slot = p % STAGES;
        CP_WAIT2();
        __syncthreads();
        const uint32_t* As = smu + slot * STAGEU;
        const uint32_t* Bs = As + TILEU;

#pragma unroll
        for (int ks = 0; ks < 2; ks++) {
            uint32_t a[2][4], b[8][2];
#pragma unroll
            for (int i = 0; i < 2; i++) {
                int base = (m0 + i * 16 + g) * STRIDEU + ks * 8 + t;
                a[i][0] = As[base];
                a[i][1] = As[base + 8 * STRIDEU];
                a[i][2] = As[base + 4];
                a[i][3] = As[base + 8 * STRIDEU + 4];
            }
#pragma unroll
            for (int j = 0; j < 8; j++) {
                int bb = (n0 + j * 8 + g) * STRIDEU + ks * 8 + t;
                b[j][0] = Bs[bb];
                b[j][1] = Bs[bb + 4];
            }
#pragma unroll
            for (int i = 0; i < 2; i++)
#pragma unroll
                for (int j = 0; j < 8; j++)
                    mma_bf16(acc[i][j], a[i], b[j]);
        }
        __syncthreads();

        int np = p + STAGES;
        if (np < P) {
            uint32_t stb = sb + slot * STAGEU * 4;
#pragma unroll
            for (int j = 0; j < 2; j++) {
                int row = lrow + j * 64;
                uint32_t sa = stb + (row * STRIDEU + lc4 * 4) * 4;
                int ar = bm + row;
                if (ar < M) cp16(sa, A + (size_t)ar * KU + np * 16 + lc4 * 4);
                else        sts_zero16(sa);
                uint32_t sbB = stb + TILEU * 4 + (row * STRIDEU + lc4 * 4) * 4;
                cp16(sbB, Bt + (size_t)(bn + row) * KU + np * 16 + lc4 * 4);
            }
        }
        CP_COMMIT();   // empty groups at tail keep wait_group accounting uniform
    }

    // ---- epilogue: pack fp32 accumulators to bf16x2 ----
#pragma unroll
    for (int i = 0; i < 2; i++) {
        int r0 = bm + m0 + i * 16 + g;
#pragma unroll
        for (int j = 0; j < 8; j++) {
            int colu = ((bn + n0 + j * 8) >> 1) + t;   // u32 column
            if (r0 < M)
                C[(size_t)r0 * NCU + colu] = pack_bf16x2(acc[i][j][0], acc[i][j][1]);
            if (r0 + 8 < M)
                C[(size_t)(r0 + 8) * NCU + colu] = pack_bf16x2(acc[i][j][2], acc[i][j][3]);
        }
    }
}

// ---------------- CSR build ----------------
__global__ void zero_cnt() {
    int i = blockIdx.x * blockDim.x + threadIdx.x;
    if (i < NN) g_cnt[i] = 0;
}
__global__ void hist_kernel(const int* __restrict__ trg) {
    int e = blockIdx.x * blockDim.x + threadIdx.x;
    if (e < EE) atomicAdd(&g_cnt[trg[e]], 1);
}
#define SCAN_CH 20
__global__ __launch_bounds__(1024) void scan_kernel(int t) {
    __shared__ int part[1024];
    int tid = threadIdx.x;
    int base = tid * SCAN_CH;
    int loc[SCAN_CH];
    int s = 0;
#pragma unroll
    for (int i = 0; i < SCAN_CH; i++) {
        int idx = base + i;
        int v = (idx < NN) ? g_cnt[idx] : 0;
        loc[i] = s;
        s += v;
    }
    part[tid] = s;
    __syncthreads();
    for (int d = 1; d < 1024; d <<= 1) {
        int v = (tid >= d) ? part[tid - d] : 0;
        __syncthreads();
        part[tid] += v;
        __syncthreads();
    }
    int excl = part[tid] - s;
#pragma unroll
    for (int i = 0; i < SCAN_CH; i++) {
        int idx = base + i;
        if (idx < NN) {
            int v = loc[i] + excl;
            g_rowptr[t][idx] = v;
            g_woff[idx] = v;
        }
    }
    if (tid == 1023) g_rowptr[t][NN] = part[1023];
}
__global__ void fill_kernel(const int* __restrict__ src, const int* __restrict__ trg, int t) {
    int e = blockIdx.x * blockDim.x + threadIdx.x;
    if (e >= EE) return;
    int p = atomicAdd(&g_woff[trg[e]], 1);
    g_csr[t][p] = src[e];
}

// ---------------- s/t projections (hp is bf16-packed) ----------------
__global__ void st_kernel(const uint32_t* __restrict__ hp,
                          const float* __restrict__ asrc,
                          const float* __restrict__ atrg) {
    int idx = blockIdx.x * blockDim.x + threadIdx.x;
    if (idx >= NN * HH) return;
    int h = idx & 7;
    const uint4* v = (const uint4*)(hp + (size_t)idx * 32);   // 8 uint4 = 64 bf16
    const float4* a = (const float4*)(asrc + h * 64);
    const float4* b = (const float4*)(atrg + h * 64);
    float s = 0.f, t = 0.f;
#pragma unroll
    for (int q = 0; q < 8; q++) {
        uint4 pk = v[q];
        float4 a0 = a[2 * q], a1 = a[2 * q + 1];
        float4 b0 = b[2 * q], b1 = b[2 * q + 1];
        float f0 = bf_lo(pk.x), f1 = bf_hi(pk.x);
        float f2 = bf_lo(pk.y), f3 = bf_hi(pk.y);
        float f4 = bf_lo(pk.z), f5 = bf_hi(pk.z);
        float f6 = bf_lo(pk.w), f7 = bf_hi(pk.w);
        s += f0 * a0.x + f1 * a0.y + f2 * a0.z + f3 * a0.w
           + f4 * a1.x + f5 * a1.y + f6 * a1.z + f7 * a1.w;
        t += f0 * b0.x + f1 * b0.y + f2 * b0.z + f3 * b0.w
           + f4 * b1.x + f5 * b1.y + f6 * b1.z + f7 * b1.w;
    }
    g_s[idx] = s;
    g_t[idx] = t;
}

// ---------------- gather-aggregate: ONE warp per target node (round-9 structure) ----------------
// mode 0: fp32 out.  mode 1: ELU + bf16-packed out.
__global__ __launch_bounds__(256) void gather_agg(const int* __restrict__ csr,
                                                  const int* __restrict__ rowptr,
                                                  const uint32_t* __restrict__ hp,
                                                  void* __restrict__ outp,
                                                  int mode)
{
    int node = (blockIdx.x * 256 + threadIdx.x) >> 5;
    int lane = threadIdx.x & 31;
    if (node >= NN) return;
    int beg = rowptr[node], end = rowptr[node + 1];

    float tval = (lane < 8) ? g_t[node * 8 + lane] : 0.f;
    float denom = 0.f;                       // lanes 0..7: per-head denominator
    float acc[2][8];
#pragma unroll
    for (int j = 0; j < 2; j++)
#pragma unroll
        for (int k = 0; k < 8; k++) acc[j][k] = 0.f;

    int srcp = (beg < end) ? csr[beg] : 0;
    for (int p = beg; p < end; p++) {
        int nxt = (p + 1 < end) ? csr[p + 1] : 0;
        float ex = 0.f;
        if (lane < 8) {
            float v = g_s[srcp * 8 + lane] + tval;
            ex = __expf(fmaxf(v, 0.2f * v));   // global max-shift cancels in alpha
            denom += ex;
        }
        const uint4* hv = (const uint4*)(hp + (size_t)srcp * 256);
#pragma unroll
        for (int j = 0; j < 2; j++) {
            int c = lane + 32 * j;               // uint4 chunk 0..63 (8 bf16 each)
            float al = __shfl_sync(0xffffffffu, ex, c >> 3);   // head = c/8
            uint4 v = hv[c];
            acc[j][0] += al * bf_lo(v.x); acc[j][1] += al * bf_hi(v.x);
            acc[j][2] += al * bf_lo(v.y); acc[j][3] += al * bf_hi(v.y);
            acc[j][4] += al * bf_lo(v.z); acc[j][5] += al * bf_hi(v.z);
            acc[j][6] += al * bf_lo(v.w); acc[j][7] += al * bf_hi(v.w);
        }
        srcp = nxt;
    }

#pragma unroll
    for (int j = 0; j < 2; j++) {
        int c = lane + 32 * j;
        float dn = __shfl_sync(0xffffffffu, denom, c >> 3) + 1e-16f;
        float inv = 1.f / dn;
        float v0 = acc[j][0] * inv, v1 = acc[j][1] * inv;
        float v2 = acc[j][2] * inv, v3 = acc[j][3] * inv;
        float v4 = acc[j][4] * inv, v5 = acc[j][5] * inv;
        float v6 = acc[j][6] * inv, v7 = acc[j][7] * inv;
        if (mode == 0) {
            float* out = (float*)outp;
            float4* ob = (float4*)(out + (size_t)node * 512 + c * 8);
            ob[0] = make_float4(v0, v1, v2, v3);
            ob[1] = make_float4(v4, v5, v6, v7);
        } else {
            uint32_t* out = (uint32_t*)outp;
            uint4 pk;
            pk.x = pack_bf16x2(eluf(v0), eluf(v1));
            pk.y = pack_bf16x2(eluf(v2), eluf(v3));
            pk.z = pack_bf16x2(eluf(v4), eluf(v5));
            pk.w = pack_bf16x2(eluf(v6), eluf(v7));
            ((uint4*)(out + (size_t)node * 256))[c] = pk;
        }
    }
}

// ---------------- prep kernels ----------------
// pack fp32 pairs -> bf16x2
__global__ void pack_bf16_k(uint32_t* __restrict__ dst, const float* __restrict__ src, int n2) {
    int i = blockIdx.x * blockDim.x + threadIdx.x;
    if (i < n2) dst[i] = pack_bf16x2(src[2 * i], src[2 * i + 1]);
}
// W [128,256] -> Wt u32 [256][64]: Wt[n][ku] = pack(W[2ku][n], W[2ku+1][n])
__global__ void transpose_pack(uint32_t* __restrict__ Wt, const float* __restrict__ W) {
    int i = blockIdx.x * blockDim.x + threadIdx.x;
    if (i >= 256 * 64) return;
    int n = i >> 6, ku = i & 63;
    Wt[i] = pack_bf16x2(W[(2 * ku) * 256 + n], W[(2 * ku + 1) * 256 + n]);
}
// w (H, fin, 64) -> Bt u32 [512][fin/2]: Bt[h*64+o][ku] = pack(w[h][2ku][o], w[h][2ku+1][o])
__global__ void repack_pack(uint32_t* __restrict__ Bt, const float* __restrict__ w, int fin) {
    int finu = fin >> 1;
    int i = blockIdx.x * blockDim.x + threadIdx.x;
    if (i >= 512 * finu) return;
    int n = i / finu, ku = i % finu;
    int h = n >> 6, o = n & 63;
    int k0 = 2 * ku;
    Bt[i] = pack_bf16x2(w[((size_t)(h * fin + k0) << 6) + o],
                        w[((size_t)(h * fin + k0 + 1) << 6) + o]);
}

__global__ void fa_kernel(const uint32_t* __restrict__ trans1, const float* __restrict__ aw1) {
    int o = threadIdx.x;
    float acc = 0.f;
    for (int f2 = 0; f2 < 128; f2++) {
        uint32_t u = trans1[f2];
        acc += bf_lo(u) * aw1[(2 * f2) * 64 + o] + bf_hi(u) * aw1[(2 * f2 + 1) * 64 + o];
    }
    g_fa[o] = acc;
}

__global__ __launch_bounds__(64) void final_kernel(const float* __restrict__ aw2,
                                                   const float* __restrict__ am,
                                                   const float* __restrict__ fcw,
                                                   const float* __restrict__ fcb,
                                                   float* __restrict__ out) {
    __shared__ float ta[2][64];
    __shared__ float r0[64], r1[64];
    __shared__ float sc[2];
    int n = blockIdx.x, o = threadIdx.x;

    float m0 = 0.f, m1 = 0.f;
    const float* p0 = g_o1a + (size_t)n * 512 + o;
    const float* p1 = g_o1b + (size_t)n * 512 + o;
#pragma unroll
    for (int h = 0; h < 8; h++) { m0 += p0[h * 64]; m1 += p1[h * 64]; }
    m0 *= 0.125f; m1 *= 0.125f;
    ta[0][o] = m0; ta[1][o] = m1;
    __syncthreads();

    float amo = am[o];
    float fa = g_fa[o];
    {
        float acc0 = fa, acc1 = fa;
        for (int d = 0; d < 64; d++) {
            float w = aw2[d * 64 + o];
            acc0 += ta[0][d] * w;
            acc1 += ta[1][d] * w;
        }
        r0[o] = tanhf(acc0) * amo;
        r1[o] = tanhf(acc1) * amo;
    }
    __syncthreads();
    if (o == 0) {
        float s0 = 0.f, s1 = 0.f;
        for (int d = 0; d < 64; d++) { s0 += r0[d]; s1 += r1[d]; }
        sc[0] = s0; sc[1] = s1;
    }
    __syncthreads();
    float mx = fmaxf(sc[0], sc[1]);
    float b0 = __expf(sc[0] - mx), b1 = __expf(sc[1] - mx);
    float inv = 1.f / (b0 + b1);
    b0 *= inv; b1 *= inv;
    float fus = b0 * m0 + b1 * m1;

    r0[o] = m0 * fcw[o * 2 + 0] + m1 * fcw[(64 + o) * 2 + 0] + fus * fcw[(128 + o) * 2 + 0];
    r1[o] = m0 * fcw[o * 2 + 1] + m1 * fcw[(64 + o) * 2 + 1] + fus * fcw[(128 + o) * 2 + 1];
    __syncthreads();
    if (o == 0) {
        float l0 = fcb[0], l1 = fcb[1];
        for (int d = 0; d < 64; d++) { l0 += r0[d]; l1 += r1[d]; }
        float m = fmaxf(l0, l1);
        float lse = m + logf(__expf(l0 - m) + __expf(l1 - m));
        out[n * 2 + 0] = l0 - lse;
        out[n * 2 + 1] = l1 - lse;
    }
}

// ---------------- launcher ----------------
extern "C" void kernel_launch(void* const* d_in, const int* in_sizes, int n_in,
                              void* d_out, int out_size)
{
    const float* hemb0 = (const float*)d_in[0];
    const float* hemb1 = (const float*)d_in[1];
    const float* W0    = (const float*)d_in[2];
    const float* W1    = (const float*)d_in[3];
    const float* gw[2][2]    = {{(const float*)d_in[4],  (const float*)d_in[7]},
                                {(const float*)d_in[10], (const float*)d_in[13]}};
    const float* gasrc[2][2] = {{(const float*)d_in[5],  (const float*)d_in[8]},
                                {(const float*)d_in[11], (const float*)d_in[14]}};
    const float* gatrg[2][2] = {{(const float*)d_in[6],  (const float*)d_in[9]},
                                {(const float*)d_in[12], (const float*)d_in[15]}};
    const float* aw1 = (const float*)d_in[16];
    const float* aw2 = (const float*)d_in[17];
    const float* am  = (const float*)d_in[18];
    const float* fcw = (const float*)d_in[19];
    const float* fcb = (const float*)d_in[20];
    const int* edge[2] = {(const int*)d_in[21], (const int*)d_in[22]};

    uint32_t *trans[2], *Bp, *hp, *x0;
    float *o1[2];
    int *csr[2], *rowptr[2];
    cudaGetSymbolAddress((void**)&trans[0], g_trans0);
    cudaGetSymbolAddress((void**)&trans[1], g_trans1);
    cudaGetSymbolAddress((void**)&Bp,  g_Bp);
    cudaGetSymbolAddress((void**)&hp,  g_hp);
    cudaGetSymbolAddress((void**)&x0,  g_x0);
    cudaGetSymbolAddress((void**)&o1[0], g_o1a);
    cudaGetSymbolAddress((void**)&o1[1], g_o1b);
    {
        int* base;
        cudaGetSymbolAddress((void**)&base, g_csr);
        csr[0] = base; csr[1] = base + EE;
        cudaGetSymbolAddress((void**)&base, g_rowptr);
        rowptr[0] = base; rowptr[1] = base + (NN + 1);
    }

    cudaFuncSetAttribute(gemm_bf16, cudaFuncAttributeMaxDynamicSharedMemorySize, SMEM_GEMM);

    const dim3 gridT(FUNI / 128, (NN + 127) / 128);
    const dim3 gridH(HF / 128,  (NN + 127) / 128);
    const int gatherBlocks = (NN * 32 + 255) / 256;   // one warp per node

    // CSR build (per type; reused by both layers)
    for (int t = 0; t < 2; t++) {
        const int* src = edge[t];
        const int* trg = edge[t] + EE;
        zero_cnt<<<(NN + 255) / 256, 256>>>();
        hist_kernel<<<(EE + 255) / 256, 256>>>(trg);
        scan_kernel<<<1, 1024>>>(t);
        fill_kernel<<<(EE + 255) / 256, 256>>>(src, trg, t);
    }

    // pack hemb inputs to bf16 (x0 and hp are free this early)
    pack_bf16_k<<<(NN * 64 + 255) / 256, 256>>>(x0, hemb0, NN * 64);
    pack_bf16_k<<<(NN * 64 + 255) / 256, 256>>>(hp, hemb1, NN * 64);

    // trans GEMMs
    transpose_pack<<<(256 * 64 + 255) / 256, 256>>>(Bp, W0);
    gemm_bf16<<<gridT, 256, SMEM_GEMM>>>(x0, Bp, trans[0], NN, 128, FUNI);
    transpose_pack<<<(256 * 64 + 255) / 256, 256>>>(Bp, W1);
    gemm_bf16<<<gridT, 256, SMEM_GEMM>>>(hp, Bp, trans[1], NN, 128, FUNI);

    for (int t = 0; t < 2; t++) {
        // ---- layer 0 (fin = 256); ELU + bf16 pack fused into gather ----
        repack_pack<<<(512 * 128 + 255) / 256, 256>>>(Bp, gw[t][0], FUNI);
        gemm_bf16<<<gridH, 256, SMEM_GEMM>>>(trans[t], Bp, hp, NN, FUNI, HF);
        st_kernel<<<(NN * HH + 255) / 256, 256>>>(hp, gasrc[t][0], gatrg[t][0]);
        gather_agg<<<gatherBlocks, 256>>>(csr[t], rowptr[t], hp, x0, 1);

        // ---- layer 1 (fin = 512), fp32 output for the final stage ----
        repack_pack<<<(512 * 256 + 255) / 256, 256>>>(Bp, gw[t][1], HF);
        gemm_bf16<<<gridH, 256, SMEM_GEMM>>>(x0, Bp, hp, NN, HF, HF);
        st_kernel<<<(NN * HH + 255) / 256, 256>>>(hp, gasrc[t][1], gatrg[t][1]);
        gather_agg<<<gatherBlocks, 256>>>(csr[t], rowptr[t], hp, o1[t], 0);
    }

    fa_kernel<<<1, 64>>>(trans[1], aw1);
    final_kernel<<<NN, 64>>>(aw2, am, fcw, fcb, (float*)d_out);
}

// round 12
// speedup vs baseline: 1.8257x; 1.2054x over previous
#include <cuda_runtime.h>
#include <cstdint>
#include <cstddef>

#define NN   20000
#define EE   320000
#define HH   8
#define FUNI 256
#define FOUT 64
#define HF   512   // H*FOUT

// ---------------- scratch (device globals; no runtime allocation) ----------------
// Per-type duplicated so the two type chains can run on concurrent streams.
__device__ uint32_t g_trans[2][NN * FUNI / 2];   // bf16x2
__device__ uint32_t g_Bpd[2][512 * 256];         // repacked weights, bf16x2
__device__ uint32_t g_hpd[2][NN * HF / 2];       // projected features (bf16); packed emb early
__device__ uint32_t g_x0d[2][NN * HF / 2];       // layer-0 aggregated (bf16, ELU'd)
__device__ float g_o1a[NN * HF];                 // layer-1 aggregated, type 0 (fp32)
__device__ float g_o1b[NN * HF];                 // layer-1 aggregated, type 1 (fp32)
__device__ float g_sd[2][NN * HH];
__device__ float g_td[2][NN * HH];
__device__ float g_fa[FOUT];

// CSR scratch (per type)
__device__ int g_cntd[2][NN];
__device__ int g_rowptr[2][NN + 1];
__device__ int g_woffd[2][NN];
__device__ int g_csr[2][EE];

// ---------------- static stream/event context (created at load, NOT during capture) ----
struct HxCtx {
    cudaStream_t s1;
    cudaEvent_t e0, e1;
    HxCtx() {
        cudaStreamCreateWithFlags(&s1, cudaStreamNonBlocking);
        cudaEventCreateWithFlags(&e0, cudaEventDisableTiming);
        cudaEventCreateWithFlags(&e1, cudaEventDisableTiming);
    }
};
static HxCtx g_hx;

// ---------------- helpers ----------------
__device__ __forceinline__ uint32_t smem_to_u32(const void* p) {
    uint32_t a;
    asm("{ .reg .u64 t; cvta.to.shared.u64 t, %1; cvt.u32.u64 %0, t; }" : "=r"(a) : "l"(p));
    return a;
}
__device__ __forceinline__ void cp16(uint32_t saddr, const void* g) {
    asm volatile("cp.async.cg.shared.global [%0], [%1], 16;" :: "r"(saddr), "l"(g));
}
__device__ __forceinline__ void sts_zero16(uint32_t saddr) {
    asm volatile("st.shared.v4.b32 [%0], {%1,%1,%1,%1};" :: "r"(saddr), "r"(0u));
}
#define CP_COMMIT() asm volatile("cp.async.commit_group;" ::: "memory")
#define CP_WAIT2()  asm volatile("cp.async.wait_group 2;" ::: "memory")

__device__ __forceinline__ uint32_t pack_bf16x2(float a, float b) {
    uint32_t r;
    asm("cvt.rn.bf16x2.f32 %0, %1, %2;" : "=r"(r) : "f"(b), "f"(a));
    return r;
}
__device__ __forceinline__ float bf_lo(uint32_t u) { return __uint_as_float(u << 16); }
__device__ __forceinline__ float bf_hi(uint32_t u) { return __uint_as_float(u & 0xffff0000u); }
__device__ __forceinline__ float eluf(float x) { return x > 0.f ? x : (__expf(x) - 1.f); }

__device__ __forceinline__ void mma_bf16(float* c, const uint32_t* a, const uint32_t* b) {
    asm volatile("mma.sync.aligned.m16n8k16.row.col.f32.bf16.bf16.f32 "
                 "{%0,%1,%2,%3}, {%4,%5,%6,%7}, {%8,%9}, {%0,%1,%2,%3};"
                 : "+f"(c[0]), "+f"(c[1]), "+f"(c[2]), "+f"(c[3])
                 : "r"(a[0]), "r"(a[1]), "r"(a[2]), "r"(a[3]), "r"(b[0]), "r"(b[1]));
}

// ---------------- bf16 mma GEMM: C[M,NC] = A[M,K] @ Bt[NC,K]^T (bf16x2-packed) ----------------
#define STAGES  3
#define STRIDEU 20
#define TILEU   (128 * STRIDEU)
#define STAGEU  (2 * TILEU)
#define SMEM_GEMM (STAGES * STAGEU * 4)    // 61440 bytes

__global__ __launch_bounds__(256, 2)
void gemm_bf16(const uint32_t* __restrict__ A, const uint32_t* __restrict__ Bt,
               uint32_t* __restrict__ C, int M, int K, int NC)
{
    extern __shared__ uint32_t smu[];
    const int tid  = threadIdx.x;
    const int wid  = tid >> 5, lane = tid & 31;
    const int g    = lane >> 2, t = lane & 3;
    const int bm   = blockIdx.y << 7, bn = blockIdx.x << 7;
    const int m0   = (wid >> 1) * 32;
    const int n0   = (wid & 1) * 64;
    const int KU   = K >> 1;
    const int NCU  = NC >> 1;
    const int P    = K >> 5;

    const uint32_t sb = smem_to_u32(smu);
    const int lrow = tid >> 2;
    const int lc4  = tid & 3;

    float acc[2][8][4];
#pragma unroll
    for (int i = 0; i < 2; i++)
#pragma unroll
        for (int j = 0; j < 8; j++)
#pragma unroll
            for (int q = 0; q < 4; q++) acc[i][j][q] = 0.f;

#pragma unroll
    for (int s = 0; s < STAGES; s++) {
        uint32_t stb = sb + s * STAGEU * 4;
#pragma unroll
        for (int j = 0; j < 2; j++) {
            int row = lrow + j * 64;
            uint32_t sa = stb + (row * STRIDEU + lc4 * 4) * 4;
            int ar = bm + row;
            if (ar < M) cp16(sa, A + (size_t)ar * KU + s * 16 + lc4 * 4);
            else        sts_zero16(sa);
            uint32_t sbB = stb + TILEU * 4 + (row * STRIDEU + lc4 * 4) * 4;
            cp16(sbB, Bt + (size_t)(bn + row) * KU + s * 16 + lc4 * 4);
        }
        CP_COMMIT();
    }

    for (int p = 0; p < P; p++) {
        const int slot = p % STAGES;
        CP_WAIT2();
        __syncthreads();
        const uint32_t* As = smu + slot * STAGEU;
        const uint32_t* Bs = As + TILEU;

#pragma unroll
        for (int ks = 0; ks < 2; ks++) {
            uint32_t a[2][4], b[8][2];
#pragma unroll
            for (int i = 0; i < 2; i++) {
                int base = (m0 + i * 16 + g) * STRIDEU + ks * 8 + t;
                a[i][0] = As[base];
                a[i][1] = As[base + 8 * STRIDEU];
                a[i][2] = As[base + 4];
                a[i][3] = As[base + 8 * STRIDEU + 4];
            }
#pragma unroll
            for (int j = 0; j < 8; j++) {
                int bb = (n0 + j * 8 + g) * STRIDEU + ks * 8 + t;
                b[j][0] = Bs[bb];
                b[j][1] = Bs[bb + 4];
            }
#pragma unroll
            for (int i = 0; i < 2; i++)
#pragma unroll
                for (int j = 0; j < 8; j++)
                    mma_bf16(acc[i][j], a[i], b[j]);
        }
        __syncthreads();

        int np = p + STAGES;
        if (np < P) {
            uint32_t stb = sb + slot * STAGEU * 4;
#pragma unroll
            for (int j = 0; j < 2; j++) {
                int row = lrow + j * 64;
                uint32_t sa = stb + (row * STRIDEU + lc4 * 4) * 4;
                int ar = bm + row;
                if (ar < M) cp16(sa, A + (size_t)ar * KU + np * 16 + lc4 * 4);
                else        sts_zero16(sa);
                uint32_t sbB = stb + TILEU * 4 + (row * STRIDEU + lc4 * 4) * 4;
                cp16(sbB, Bt + (size_t)(bn + row) * KU + np * 16 + lc4 * 4);
            }
        }
        CP_COMMIT();
    }

#pragma unroll
    for (int i = 0; i < 2; i++) {
        int r0 = bm + m0 + i * 16 + g;
#pragma unroll
        for (int j = 0; j < 8; j++) {
            int colu = ((bn + n0 + j * 8) >> 1) + t;
            if (r0 < M)
                C[(size_t)r0 * NCU + colu] = pack_bf16x2(acc[i][j][0], acc[i][j][1]);
            if (r0 + 8 < M)
                C[(size_t)(r0 + 8) * NCU + colu] = pack_bf16x2(acc[i][j][2], acc[i][j][3]);
        }
    }
}

// ---------------- CSR build (per type t) ----------------
__global__ void zero_cnt(int t) {
    int i = blockIdx.x * blockDim.x + threadIdx.x;
    if (i < NN) g_cntd[t][i] = 0;
}
__global__ void hist_kernel(const int* __restrict__ trg, int t) {
    int e = blockIdx.x * blockDim.x + threadIdx.x;
    if (e < EE) atomicAdd(&g_cntd[t][trg[e]], 1);
}
#define SCAN_CH 20
__global__ __launch_bounds__(1024) void scan_kernel(int t) {
    __shared__ int part[1024];
    int tid = threadIdx.x;
    int base = tid * SCAN_CH;
    int loc[SCAN_CH];
    int s = 0;
#pragma unroll
    for (int i = 0; i < SCAN_CH; i++) {
        int idx = base + i;
        int v = (idx < NN) ? g_cntd[t][idx] : 0;
        loc[i] = s;
        s += v;
    }
    part[tid] = s;
    __syncthreads();
    for (int d = 1; d < 1024; d <<= 1) {
        int v = (tid >= d) ? part[tid - d] : 0;
        __syncthreads();
        part[tid] += v;
        __syncthreads();
    }
    int excl = part[tid] - s;
#pragma unroll
    for (int i = 0; i < SCAN_CH; i++) {
        int idx = base + i;
        if (idx < NN) {
            int v = loc[i] + excl;
            g_rowptr[t][idx] = v;
            g_woffd[t][idx] = v;
        }
    }
    if (tid == 1023) g_rowptr[t][NN] = part[1023];
}
__global__ void fill_kernel(const int* __restrict__ src, const int* __restrict__ trg, int t) {
    int e = blockIdx.x * blockDim.x + threadIdx.x;
    if (e >= EE) return;
    int p = atomicAdd(&g_woffd[t][trg[e]], 1);
    g_csr[t][p] = src[e];
}

// ---------------- s/t projections (hp bf16-packed) ----------------
__global__ void st_kernel(const uint32_t* __restrict__ hp,
                          const float* __restrict__ asrc,
                          const float* __restrict__ atrg,
                          float* __restrict__ sArr, float* __restrict__ tArr) {
    int idx = blockIdx.x * blockDim.x + threadIdx.x;
    if (idx >= NN * HH) return;
    int h = idx & 7;
    const uint4* v = (const uint4*)(hp + (size_t)idx * 32);
    const float4* a = (const float4*)(asrc + h * 64);
    const float4* b = (const float4*)(atrg + h * 64);
    float s = 0.f, t = 0.f;
#pragma unroll
    for (int q = 0; q < 8; q++) {
        uint4 pk = v[q];
        float4 a0 = a[2 * q], a1 = a[2 * q + 1];
        float4 b0 = b[2 * q], b1 = b[2 * q + 1];
        float f0 = bf_lo(pk.x), f1 = bf_hi(pk.x);
        float f2 = bf_lo(pk.y), f3 = bf_hi(pk.y);
        float f4 = bf_lo(pk.z), f5 = bf_hi(pk.z);
        float f6 = bf_lo(pk.w), f7 = bf_hi(pk.w);
        s += f0 * a0.x + f1 * a0.y + f2 * a0.z + f3 * a0.w
           + f4 * a1.x + f5 * a1.y + f6 * a1.z + f7 * a1.w;
        t += f0 * b0.x + f1 * b0.y + f2 * b0.z + f3 * b0.w
           + f4 * b1.x + f5 * b1.y + f6 * b1.z + f7 * b1.w;
    }
    sArr[idx] = s;
    tArr[idx] = t;
}

// ---------------- gather-aggregate: one warp per target node ----------------
// mode 0: fp32 out.  mode 1: ELU + bf16-packed out.
__global__ __launch_bounds__(256) void gather_agg(const int* __restrict__ csr,
                                                  const int* __restrict__ rowptr,
                                                  const uint32_t* __restrict__ hp,
                                                  const float* __restrict__ sArr,
                                                  const float* __restrict__ tArr,
                                                  void* __restrict__ outp,
                                                  int mode)
{
    int node = (blockIdx.x * 256 + threadIdx.x) >> 5;
    int lane = threadIdx.x & 31;
    if (node >= NN) return;
    int beg = rowptr[node], end = rowptr[node + 1];

    float tval = (lane < 8) ? tArr[node * 8 + lane] : 0.f;
    float denom = 0.f;
    float acc[2][8];
#pragma unroll
    for (int j = 0; j < 2; j++)
#pragma unroll
        for (int k = 0; k < 8; k++) acc[j][k] = 0.f;

    int srcp = (beg < end) ? csr[beg] : 0;
    for (int p = beg; p < end; p++) {
        int nxt = (p + 1 < end) ? csr[p + 1] : 0;
        float ex = 0.f;
        if (lane < 8) {
            float v = sArr[srcp * 8 + lane] + tval;
            ex = __expf(fmaxf(v, 0.2f * v));   // global max-shift cancels in alpha
            denom += ex;
        }
        const uint4* hv = (const uint4*)(hp + (size_t)srcp * 256);
#pragma unroll
        for (int j = 0; j < 2; j++) {
            int c = lane + 32 * j;
            float al = __shfl_sync(0xffffffffu, ex, c >> 3);
            uint4 v = hv[c];
            acc[j][0] += al * bf_lo(v.x); acc[j][1] += al * bf_hi(v.x);
            acc[j][2] += al * bf_lo(v.y); acc[j][3] += al * bf_hi(v.y);
            acc[j][4] += al * bf_lo(v.z); acc[j][5] += al * bf_hi(v.z);
            acc[j][6] += al * bf_lo(v.w); acc[j][7] += al * bf_hi(v.w);
        }
        srcp = nxt;
    }

#pragma unroll
    for (int j = 0; j < 2; j++) {
        int c = lane + 32 * j;
        float dn = __shfl_sync(0xffffffffu, denom, c >> 3) + 1e-16f;
        float inv = 1.f / dn;
        float v0 = acc[j][0] * inv, v1 = acc[j][1] * inv;
        float v2 = acc[j][2] * inv, v3 = acc[j][3] * inv;
        float v4 = acc[j][4] * inv, v5 = acc[j][5] * inv;
        float v6 = acc[j][6] * inv, v7 = acc[j][7] * inv;
        if (mode == 0) {
            float* out = (float*)outp;
            float4* ob = (float4*)(out + (size_t)node * 512 + c * 8);
            ob[0] = make_float4(v0, v1, v2, v3);
            ob[1] = make_float4(v4, v5, v6, v7);
        } else {
            uint32_t* out = (uint32_t*)outp;
            uint4 pk;
            pk.x = pack_bf16x2(eluf(v0), eluf(v1));
            pk.y = pack_bf16x2(eluf(v2), eluf(v3));
            pk.z = pack_bf16x2(eluf(v4), eluf(v5));
            pk.w = pack_bf16x2(eluf(v6), eluf(v7));
            ((uint4*)(out + (size_t)node * 256))[c] = pk;
        }
    }
}

// ---------------- prep kernels ----------------
__global__ void pack_bf16_k(uint32_t* __restrict__ dst, const float* __restrict__ src, int n2) {
    int i = blockIdx.x * blockDim.x + threadIdx.x;
    if (i < n2) dst[i] = pack_bf16x2(src[2 * i], src[2 * i + 1]);
}
__global__ void transpose_pack(uint32_t* __restrict__ Wt, const float* __restrict__ W) {
    int i = blockIdx.x * blockDim.x + threadIdx.x;
    if (i >= 256 * 64) return;
    int n = i >> 6, ku = i & 63;
    Wt[i] = pack_bf16x2(W[(2 * ku) * 256 + n], W[(2 * ku + 1) * 256 + n]);
}
__global__ void repack_pack(uint32_t* __restrict__ Bt, const float* __restrict__ w, int fin) {
    int finu = fin >> 1;
    int i = blockIdx.x * blockDim.x + threadIdx.x;
    if (i >= 512 * finu) return;
    int n = i / finu, ku = i % finu;
    int h = n >> 6, o = n & 63;
    int k0 = 2 * ku;
    Bt[i] = pack_bf16x2(w[((size_t)(h * fin + k0) << 6) + o],
                        w[((size_t)(h * fin + k0 + 1) << 6) + o]);
}

__global__ void fa_kernel(const uint32_t* __restrict__ trans1, const float* __restrict__ aw1) {
    int o = threadIdx.x;
    float acc = 0.f;
    for (int f2 = 0; f2 < 128; f2++) {
        uint32_t u = trans1[f2];
        acc += bf_lo(u) * aw1[(2 * f2) * 64 + o] + bf_hi(u) * aw1[(2 * f2 + 1) * 64 + o];
    }
    g_fa[o] = acc;
}

__global__ __launch_bounds__(64) void final_kernel(const float* __restrict__ aw2,
                                                   const float* __restrict__ am,
                                                   const float* __restrict__ fcw,
                                                   const float* __restrict__ fcb,
                                                   float* __restrict__ out) {
    __shared__ float ta[2][64];
    __shared__ float r0[64], r1[64];
    __shared__ float sc[2];
    int n = blockIdx.x, o = threadIdx.x;

    float m0 = 0.f, m1 = 0.f;
    const float* p0 = g_o1a + (size_t)n * 512 + o;
    const float* p1 = g_o1b + (size_t)n * 512 + o;
#pragma unroll
    for (int h = 0; h < 8; h++) { m0 += p0[h * 64]; m1 += p1[h * 64]; }
    m0 *= 0.125f; m1 *= 0.125f;
    ta[0][o] = m0; ta[1][o] = m1;
    __syncthreads();

    float amo = am[o];
    float fa = g_fa[o];
    {
        float acc0 = fa, acc1 = fa;
        for (int d = 0; d < 64; d++) {
            float w = aw2[d * 64 + o];
            acc0 += ta[0][d] * w;
            acc1 += ta[1][d] * w;
        }
        r0[o] = tanhf(acc0) * amo;
        r1[o] = tanhf(acc1) * amo;
    }
    __syncthreads();
    if (o == 0) {
        float s0 = 0.f, s1 = 0.f;
        for (int d = 0; d < 64; d++) { s0 += r0[d]; s1 += r1[d]; }
        sc[0] = s0; sc[1] = s1;
    }
    __syncthreads();
    float mx = fmaxf(sc[0], sc[1]);
    float b0 = __expf(sc[0] - mx), b1 = __expf(sc[1] - mx);
    float inv = 1.f / (b0 + b1);
    b0 *= inv; b1 *= inv;
    float fus = b0 * m0 + b1 * m1;

    r0[o] = m0 * fcw[o * 2 + 0] + m1 * fcw[(64 + o) * 2 + 0] + fus * fcw[(128 + o) * 2 + 0];
    r1[o] = m0 * fcw[o * 2 + 1] + m1 * fcw[(64 + o) * 2 + 1] + fus * fcw[(128 + o) * 2 + 1];
    __syncthreads();
    if (o == 0) {
        float l0 = fcb[0], l1 = fcb[1];
        for (int d = 0; d < 64; d++) { l0 += r0[d]; l1 += r1[d]; }
        float m = fmaxf(l0, l1);
        float lse = m + logf(__expf(l0 - m) + __expf(l1 - m));
        out[n * 2 + 0] = l0 - lse;
        out[n * 2 + 1] = l1 - lse;
    }
}

// ---------------- launcher: fork/join two per-type chains ----------------
extern "C" void kernel_launch(void* const* d_in, const int* in_sizes, int n_in,
                              void* d_out, int out_size)
{
    const float* hemb[2] = {(const float*)d_in[0], (const float*)d_in[1]};
    const float* W[2]    = {(const float*)d_in[2], (const float*)d_in[3]};
    const float* gw[2][2]    = {{(const float*)d_in[4],  (const float*)d_in[7]},
                                {(const float*)d_in[10], (const float*)d_in[13]}};
    const float* gasrc[2][2] = {{(const float*)d_in[5],  (const float*)d_in[8]},
                                {(const float*)d_in[11], (const float*)d_in[14]}};
    const float* gatrg[2][2] = {{(const float*)d_in[6],  (const float*)d_in[9]},
                                {(const float*)d_in[12], (const float*)d_in[15]}};
    const float* aw1 = (const float*)d_in[16];
    const float* aw2 = (const float*)d_in[17];
    const float* am  = (const float*)d_in[18];
    const float* fcw = (const float*)d_in[19];
    const float* fcb = (const float*)d_in[20];
    const int* edge[2] = {(const int*)d_in[21], (const int*)d_in[22]};

    uint32_t *trans[2], *Bp[2], *hp[2], *x0[2];
    float *o1[2], *sArr[2], *tArr[2];
    int *csr[2], *rowptr[2];
    {
        uint32_t* ub;
        cudaGetSymbolAddress((void**)&ub, g_trans); trans[0] = ub; trans[1] = ub + NN * FUNI / 2;
        cudaGetSymbolAddress((void**)&ub, g_Bpd);   Bp[0] = ub;    Bp[1] = ub + 512 * 256;
        cudaGetSymbolAddress((void**)&ub, g_hpd);   hp[0] = ub;    hp[1] = ub + NN * HF / 2;
        cudaGetSymbolAddress((void**)&ub, g_x0d);   x0[0] = ub;    x0[1] = ub + NN * HF / 2;
        float* fb;
        cudaGetSymbolAddress((void**)&fb, g_o1a);   o1[0] = fb;
        cudaGetSymbolAddress((void**)&fb, g_o1b);   o1[1] = fb;
        cudaGetSymbolAddress((void**)&fb, g_sd);    sArr[0] = fb;  sArr[1] = fb + NN * HH;
        cudaGetSymbolAddress((void**)&fb, g_td);    tArr[0] = fb;  tArr[1] = fb + NN * HH;
        int* ib;
        cudaGetSymbolAddress((void**)&ib, g_csr);    csr[0] = ib;    csr[1] = ib + EE;
        cudaGetSymbolAddress((void**)&ib, g_rowptr); rowptr[0] = ib; rowptr[1] = ib + (NN + 1);
    }

    cudaFuncSetAttribute(gemm_bf16, cudaFuncAttributeMaxDynamicSharedMemorySize, SMEM_GEMM);

    const dim3 gridT(FUNI / 128, (NN + 127) / 128);
    const dim3 gridH(HF / 128,  (NN + 127) / 128);
    const int gatherBlocks = (NN * 32 + 255) / 256;   // one warp per node

    cudaStream_t str[2] = {(cudaStream_t)0, g_hx.s1};

    // fork: s1 joins the capture after the (empty) prologue on the capture stream
    cudaEventRecord(g_hx.e0, str[0]);
    cudaStreamWaitEvent(str[1], g_hx.e0, 0);

    for (int t = 0; t < 2; t++) {
        cudaStream_t s = str[t];
        const int* src = edge[t];
        const int* trg = edge[t] + EE;

        // CSR build
        zero_cnt<<<(NN + 255) / 256, 256, 0, s>>>(t);
        hist_kernel<<<(EE + 255) / 256, 256, 0, s>>>(trg, t);
        scan_kernel<<<1, 1024, 0, s>>>(t);
        fill_kernel<<<(EE + 255) / 256, 256, 0, s>>>(src, trg, t);

        // pack emb -> hp[t] (free until layer-0 GEMM overwrites it)
        pack_bf16_k<<<(NN * 64 + 255) / 256, 256, 0, s>>>(hp[t], hemb[t], NN * 64);

        // trans GEMM
        transpose_pack<<<(256 * 64 + 255) / 256, 256, 0, s>>>(Bp[t], W[t]);
        gemm_bf16<<<gridT, 256, SMEM_GEMM, s>>>(hp[t], Bp[t], trans[t], NN, 128, FUNI);

        // layer 0 (fin = 256); ELU + bf16 pack fused into gather
        repack_pack<<<(512 * 128 + 255) / 256, 256, 0, s>>>(Bp[t], gw[t][0], FUNI);
        gemm_bf16<<<gridH, 256, SMEM_GEMM, s>>>(trans[t], Bp[t], hp[t], NN, FUNI, HF);
        st_kernel<<<(NN * HH + 255) / 256, 256, 0, s>>>(hp[t], gasrc[t][0], gatrg[t][0], sArr[t], tArr[t]);
        gather_agg<<<gatherBlocks, 256, 0, s>>>(csr[t], rowptr[t], hp[t], sArr[t], tArr[t], x0[t], 1);

        // layer 1 (fin = 512), fp32 output for the final stage
        repack_pack<<<(512 * 256 + 255) / 256, 256, 0, s>>>(Bp[t], gw[t][1], HF);
        gemm_bf16<<<gridH, 256, SMEM_GEMM, s>>>(x0[t], Bp[t], hp[t], NN, HF, HF);
        st_kernel<<<(NN * HH + 255) / 256, 256, 0, s>>>(hp[t], gasrc[t][1], gatrg[t][1], sArr[t], tArr[t]);
        gather_agg<<<gatherBlocks, 256, 0, s>>>(csr[t], rowptr[t], hp[t], sArr[t], tArr[t], o1[t], 0);
    }

    // join: capture stream waits for the type-1 chain
    cudaEventRecord(g_hx.e1, str[1]);
    cudaStreamWaitEvent(str[0], g_hx.e1, 0);

    fa_kernel<<<1, 64, 0, str[0]>>>(trans[1], aw1);
    final_kernel<<<NN, 64, 0, str[0]>>>(aw2, am, fcw, fcb, (float*)d_out);
}

// round 13
// speedup vs baseline: 1.9215x; 1.0524x over previous
#include <cuda_runtime.h>
#include <cstdint>
#include <cstddef>

#define NN   20000
#define EE   320000
#define HH   8
#define FUNI 256
#define FOUT 64
#define HF   512   // H*FOUT

// ---------------- scratch (device globals; no runtime allocation) ----------------
// Per-type duplicated so the two type chains can run on concurrent streams.
__device__ uint32_t g_trans[2][NN * FUNI / 2];   // bf16x2
__device__ uint32_t g_Bpd[2][512 * 256];         // repacked weights, bf16x2
__device__ uint32_t g_hpd[2][NN * HF / 2];       // projected features (bf16); packed emb early
__device__ uint32_t g_x0d[2][NN * HF / 2];       // layer-0 aggregated (bf16, ELU'd)
__device__ float g_o1a[NN * HF];                 // layer-1 aggregated, type 0 (fp32)
__device__ float g_o1b[NN * HF];                 // layer-1 aggregated, type 1 (fp32)
__device__ float g_sd[2][NN * HH];
__device__ float g_td[2][NN * HH];
__device__ float g_fa[FOUT];

// CSR scratch (per type)
__device__ int g_cntd[2][NN];
__device__ int g_rowptr[2][NN + 1];
__device__ int g_woffd[2][NN];
__device__ int g_csr[2][EE];

// ---------------- static stream/event context (created at load, NOT during capture) ----
struct HxCtx {
    cudaStream_t s1;
    cudaEvent_t e0, e1;
    HxCtx() {
        cudaStreamCreateWithFlags(&s1, cudaStreamNonBlocking);
        cudaEventCreateWithFlags(&e0, cudaEventDisableTiming);
        cudaEventCreateWithFlags(&e1, cudaEventDisableTiming);
    }
};
static HxCtx g_hx;

// ---------------- helpers ----------------
__device__ __forceinline__ uint32_t smem_to_u32(const void* p) {
    uint32_t a;
    asm("{ .reg .u64 t; cvta.to.shared.u64 t, %1; cvt.u32.u64 %0, t; }" : "=r"(a) : "l"(p));
    return a;
}
__device__ __forceinline__ void cp16(uint32_t saddr, const void* g) {
    asm volatile("cp.async.cg.shared.global [%0], [%1], 16;" :: "r"(saddr), "l"(g));
}
__device__ __forceinline__ void sts_zero16(uint32_t saddr) {
    asm volatile("st.shared.v4.b32 [%0], {%1,%1,%1,%1};" :: "r"(saddr), "r"(0u));
}
#define CP_COMMIT() asm volatile("cp.async.commit_group;" ::: "memory")
#define CP_WAIT2()  asm volatile("cp.async.wait_group 2;" ::: "memory")

__device__ __forceinline__ uint32_t pack_bf16x2(float a, float b) {
    uint32_t r;
    asm("cvt.rn.bf16x2.f32 %0, %1, %2;" : "=r"(r) : "f"(b), "f"(a));
    return r;
}
__device__ __forceinline__ float bf_lo(uint32_t u) { return __uint_as_float(u << 16); }
__device__ __forceinline__ float bf_hi(uint32_t u) { return __uint_as_float(u & 0xffff0000u); }
__device__ __forceinline__ float eluf(float x) { return x > 0.f ? x : (__expf(x) - 1.f); }

__device__ __forceinline__ void mma_bf16(float* c, const uint32_t* a, const uint32_t* b) {
    asm volatile("mma.sync.aligned.m16n8k16.row.col.f32.bf16.bf16.f32 "
                 "{%0,%1,%2,%3}, {%4,%5,%6,%7}, {%8,%9}, {%0,%1,%2,%3};"
                 : "+f"(c[0]), "+f"(c[1]), "+f"(c[2]), "+f"(c[3])
                 : "r"(a[0]), "r"(a[1]), "r"(a[2]), "r"(a[3]), "r"(b[0]), "r"(b[1]));
}

// ---------------- bf16 mma GEMM: C[M,NC] = A[M,K] @ Bt[NC,K]^T (bf16x2-packed) ----------------
#define STAGES  3
#define STRIDEU 20
#define TILEU   (128 * STRIDEU)
#define STAGEU  (2 * TILEU)
#define SMEM_GEMM (STAGES * STAGEU * 4)    // 61440 bytes

__global__ __launch_bounds__(256, 2)
void gemm_bf16(const uint32_t* __restrict__ A, const uint32_t* __restrict__ Bt,
               uint32_t* __restrict__ C, int M, int K, int NC)
{
    extern __shared__ uint32_t smu[];
    const int tid  = threadIdx.x;
    const int wid  = tid >> 5, lane = tid & 31;
    const int g    = lane >> 2, t = lane & 3;
    const int bm   = blockIdx.y << 7, bn = blockIdx.x << 7;
    const int m0   = (wid >> 1) * 32;
    const int n0   = (wid & 1) * 64;
    const int KU   = K >> 1;
    const int NCU  = NC >> 1;
    const int P    = K >> 5;

    const uint32_t sb = smem_to_u32(smu);
    const int lrow = tid >> 2;
    const int lc4  = tid & 3;

    float acc[2][8][4];
#pragma unroll
    for (int i = 0; i < 2; i++)
#pragma unroll
        for (int j = 0; j < 8; j++)
#pragma unroll
            for (int q = 0; q < 4; q++) acc[i][j][q] = 0.f;

#pragma unroll
    for (int s = 0; s < STAGES; s++) {
        uint32_t stb = sb + s * STAGEU * 4;
#pragma unroll
        for (int j = 0; j < 2; j++) {
            int row = lrow + j * 64;
            uint32_t sa = stb + (row * STRIDEU + lc4 * 4) * 4;
            int ar = bm + row;
            if (ar < M) cp16(sa, A + (size_t)ar * KU + s * 16 + lc4 * 4);
            else        sts_zero16(sa);
            uint32_t sbB = stb + TILEU * 4 + (row * STRIDEU + lc4 * 4) * 4;
            cp16(sbB, Bt + (size_t)(bn + row) * KU + s * 16 + lc4 * 4);
        }
        CP_COMMIT();
    }

    for (int p = 0; p < P; p++) {
        const int slot = p % STAGES;
        CP_WAIT2();
        __syncthreads();
        const uint32_t* As = smu + slot * STAGEU;
        const uint32_t* Bs = As + TILEU;

#pragma unroll
        for (int ks = 0; ks < 2; ks++) {
            uint32_t a[2][4], b[8][2];
#pragma unroll
            for (int i = 0; i < 2; i++) {
                int base = (m0 + i * 16 + g) * STRIDEU + ks * 8 + t;
                a[i][0] = As[base];
                a[i][1] = As[base + 8 * STRIDEU];
                a[i][2] = As[base + 4];
                a[i][3] = As[base + 8 * STRIDEU + 4];
            }
#pragma unroll
            for (int j = 0; j < 8; j++) {
                int bb = (n0 + j * 8 + g) * STRIDEU + ks * 8 + t;
                b[j][0] = Bs[bb];
                b[j][1] = Bs[bb + 4];
            }
#pragma unroll
            for (int i = 0; i < 2; i++)
#pragma unroll
                for (int j = 0; j < 8; j++)
                    mma_bf16(acc[i][j], a[i], b[j]);
        }
        __syncthreads();

        int np = p + STAGES;
        if (np < P) {
            uint32_t stb = sb + slot * STAGEU * 4;
#pragma unroll
            for (int j = 0; j < 2; j++) {
                int row = lrow + j * 64;
                uint32_t sa = stb + (row * STRIDEU + lc4 * 4) * 4;
                int ar = bm + row;
                if (ar < M) cp16(sa, A + (size_t)ar * KU + np * 16 + lc4 * 4);
                else        sts_zero16(sa);
                uint32_t sbB = stb + TILEU * 4 + (row * STRIDEU + lc4 * 4) * 4;
                cp16(sbB, Bt + (size_t)(bn + row) * KU + np * 16 + lc4 * 4);
            }
        }
        CP_COMMIT();
    }

#pragma unroll
    for (int i = 0; i < 2; i++) {
        int r0 = bm + m0 + i * 16 + g;
#pragma unroll
        for (int j = 0; j < 8; j++) {
            int colu = ((bn + n0 + j * 8) >> 1) + t;
            if (r0 < M)
                C[(size_t)r0 * NCU + colu] = pack_bf16x2(acc[i][j][0], acc[i][j][1]);
            if (r0 + 8 < M)
                C[(size_t)(r0 + 8) * NCU + colu] = pack_bf16x2(acc[i][j][2], acc[i][j][3]);
        }
    }
}

// ---------------- CSR build (per type t) ----------------
__global__ void zero_cnt(int t) {
    int i = blockIdx.x * blockDim.x + threadIdx.x;
    if (i < NN) g_cntd[t][i] = 0;
}
__global__ void hist_kernel(const int* __restrict__ trg, int t) {
    int e = blockIdx.x * blockDim.x + threadIdx.x;
    if (e < EE) atomicAdd(&g_cntd[t][trg[e]], 1);
}
#define SCAN_CH 20
__global__ __launch_bounds__(1024) void scan_kernel(int t) {
    __shared__ int part[1024];
    int tid = threadIdx.x;
    int base = tid * SCAN_CH;
    int loc[SCAN_CH];
    int s = 0;
#pragma unroll
    for (int i = 0; i < SCAN_CH; i++) {
        int idx = base + i;
        int v = (idx < NN) ? g_cntd[t][idx] : 0;
        loc[i] = s;
        s += v;
    }
    part[tid] = s;
    __syncthreads();
    for (int d = 1; d < 1024; d <<= 1) {
        int v = (tid >= d) ? part[tid - d] : 0;
        __syncthreads();
        part[tid] += v;
        __syncthreads();
    }
    int excl = part[tid] - s;
#pragma unroll
    for (int i = 0; i < SCAN_CH; i++) {
        int idx = base + i;
        if (idx < NN) {
            int v = loc[i] + excl;
            g_rowptr[t][idx] = v;
            g_woffd[t][idx] = v;
        }
    }
    if (tid == 1023) g_rowptr[t][NN] = part[1023];
}
__global__ void fill_kernel(const int* __restrict__ src, const int* __restrict__ trg, int t) {
    int e = blockIdx.x * blockDim.x + threadIdx.x;
    if (e >= EE) return;
    int p = atomicAdd(&g_woffd[t][trg[e]], 1);
    g_csr[t][p] = src[e];
}

// ---------------- s/t projections (hp bf16-packed) ----------------
__global__ void st_kernel(const uint32_t* __restrict__ hp,
                          const float* __restrict__ asrc,
                          const float* __restrict__ atrg,
                          float* __restrict__ sArr, float* __restrict__ tArr) {
    int idx = blockIdx.x * blockDim.x + threadIdx.x;
    if (idx >= NN * HH) return;
    int h = idx & 7;
    const uint4* v = (const uint4*)(hp + (size_t)idx * 32);
    const float4* a = (const float4*)(asrc + h * 64);
    const float4* b = (const float4*)(atrg + h * 64);
    float s = 0.f, t = 0.f;
#pragma unroll
    for (int q = 0; q < 8; q++) {
        uint4 pk = v[q];
        float4 a0 = a[2 * q], a1 = a[2 * q + 1];
        float4 b0 = b[2 * q], b1 = b[2 * q + 1];
        float f0 = bf_lo(pk.x), f1 = bf_hi(pk.x);
        float f2 = bf_lo(pk.y), f3 = bf_hi(pk.y);
        float f4 = bf_lo(pk.z), f5 = bf_hi(pk.z);
        float f6 = bf_lo(pk.w), f7 = bf_hi(pk.w);
        s += f0 * a0.x + f1 * a0.y + f2 * a0.z + f3 * a0.w
           + f4 * a1.x + f5 * a1.y + f6 * a1.z + f7 * a1.w;
        t += f0 * b0.x + f1 * b0.y + f2 * b0.z + f3 * b0.w
           + f4 * b1.x + f5 * b1.y + f6 * b1.z + f7 * b1.w;
    }
    sArr[idx] = s;
    tArr[idx] = t;
}

// ---------------- gather-aggregate v2: one warp per node, 4 edges per step ----------------
// Lane mapping per 4-edge group: lane = i*8 + h handles (edge i, head h) for the
// s/exp work; alpha values are then shuffled to the chunk layout for accumulation.
// mode 0: fp32 out.  mode 1: ELU + bf16-packed out.
__global__ __launch_bounds__(256) void gather_agg(const int* __restrict__ csr,
                                                  const int* __restrict__ rowptr,
                                                  const uint32_t* __restrict__ hp,
                                                  const float* __restrict__ sArr,
                                                  const float* __restrict__ tArr,
                                                  void* __restrict__ outp,
                                                  int mode)
{
    const uint32_t FULL = 0xffffffffu;
    int node = (blockIdx.x * 256 + threadIdx.x) >> 5;
    int lane = threadIdx.x & 31;
    if (node >= NN) return;
    int beg = rowptr[node], end = rowptr[node + 1];

    const int h = lane & 7;                  // head for the s/exp phase
    const int eg = lane >> 3;                // edge-in-group (0..3)
    float tval = tArr[node * 8 + h];

    float dsum = 0.f;                        // per (eg, h) partial denominator
    float acc[2][8];
#pragma unroll
    for (int j = 0; j < 2; j++)
#pragma unroll
        for (int k = 0; k < 8; k++) acc[j][k] = 0.f;

    for (int base = beg; base < end; base += 32) {
        int nrem = end - base; if (nrem > 32) nrem = 32;
        int sv = (base + lane < end) ? csr[base + lane] : 0;   // one coalesced load / 32 edges

        for (int i4 = 0; i4 < nrem; i4 += 4) {
            // parallel s-load + exp for 4 edges x 8 heads
            int myEdge = i4 + eg;
            int srcE = __shfl_sync(FULL, sv, myEdge & 31);
            float ex = 0.f;
            if (myEdge < nrem) {
                float v = sArr[srcE * 8 + h] + tval;
                ex = __expf(fmaxf(v, 0.2f * v));   // global max-shift cancels in alpha
                dsum += ex;
            }
            // accumulate 4 edges; 8 independent uint4 loads in flight
#pragma unroll
            for (int i = 0; i < 4; i++) {
                int srcp = __shfl_sync(FULL, sv, (i4 + i) & 31);
                const uint4* hv = (const uint4*)(hp + (size_t)srcp * 256);
#pragma unroll
                for (int j = 0; j < 2; j++) {
                    int c = lane + 32 * j;
                    float al = __shfl_sync(FULL, ex, (i << 3) | (c >> 3));
                    uint4 v = hv[c];
                    acc[j][0] += al * bf_lo(v.x); acc[j][1] += al * bf_hi(v.x);
                    acc[j][2] += al * bf_lo(v.y); acc[j][3] += al * bf_hi(v.y);
                    acc[j][4] += al * bf_lo(v.z); acc[j][5] += al * bf_hi(v.z);
                    acc[j][6] += al * bf_lo(v.w); acc[j][7] += al * bf_hi(v.w);
                }
            }
        }
    }

    // reduce denominators across the 4 edge-groups (lanes h, h+8, h+16, h+24)
    dsum += __shfl_xor_sync(FULL, dsum, 8);
    dsum += __shfl_xor_sync(FULL, dsum, 16);

#pragma unroll
    for (int j = 0; j < 2; j++) {
        int c = lane + 32 * j;
        float dn = __shfl_sync(FULL, dsum, c >> 3) + 1e-16f;   // lane (c>>3) has head c>>3
        float inv = 1.f / dn;
        float v0 = acc[j][0] * inv, v1 = acc[j][1] * inv;
        float v2 = acc[j][2] * inv, v3 = acc[j][3] * inv;
        float v4 = acc[j][4] * inv, v5 = acc[j][5] * inv;
        float v6 = acc[j][6] * inv, v7 = acc[j][7] * inv;
        if (mode == 0) {
            float* out = (float*)outp;
            float4* ob = (float4*)(out + (size_t)node * 512 + c * 8);
            ob[0] = make_float4(v0, v1, v2, v3);
            ob[1] = make_float4(v4, v5, v6, v7);
        } else {
            uint32_t* out = (uint32_t*)outp;
            uint4 pk;
            pk.x = pack_bf16x2(eluf(v0), eluf(v1));
            pk.y = pack_bf16x2(eluf(v2), eluf(v3));
            pk.z = pack_bf16x2(eluf(v4), eluf(v5));
            pk.w = pack_bf16x2(eluf(v6), eluf(v7));
            ((uint4*)(out + (size_t)node * 256))[c] = pk;
        }
    }
}

// ---------------- prep kernels ----------------
__global__ void pack_bf16_k(uint32_t* __restrict__ dst, const float* __restrict__ src, int n2) {
    int i = blockIdx.x * blockDim.x + threadIdx.x;
    if (i < n2) dst[i] = pack_bf16x2(src[2 * i], src[2 * i + 1]);
}
__global__ void transpose_pack(uint32_t* __restrict__ Wt, const float* __restrict__ W) {
    int i = blockIdx.x * blockDim.x + threadIdx.x;
    if (i >= 256 * 64) return;
    int n = i >> 6, ku = i & 63;
    Wt[i] = pack_bf16x2(W[(2 * ku) * 256 + n], W[(2 * ku + 1) * 256 + n]);
}
__global__ void repack_pack(uint32_t* __restrict__ Bt, const float* __restrict__ w, int fin) {
    int finu = fin >> 1;
    int i = blockIdx.x * blockDim.x + threadIdx.x;
    if (i >= 512 * finu) return;
    int n = i / finu, ku = i % finu;
    int h = n >> 6, o = n & 63;
    int k0 = 2 * ku;
    Bt[i] = pack_bf16x2(w[((size_t)(h * fin + k0) << 6) + o],
                        w[((size_t)(h * fin + k0 + 1) << 6) + o]);
}

__global__ void fa_kernel(const uint32_t* __restrict__ trans1, const float* __restrict__ aw1) {
    int o = threadIdx.x;
    float acc = 0.f;
    for (int f2 = 0; f2 < 128; f2++) {
        uint32_t u = trans1[f2];
        acc += bf_lo(u) * aw1[(2 * f2) * 64 + o] + bf_hi(u) * aw1[(2 * f2 + 1) * 64 + o];
    }
    g_fa[o] = acc;
}

__global__ __launch_bounds__(64) void final_kernel(const float* __restrict__ aw2,
                                                   const float* __restrict__ am,
                                                   const float* __restrict__ fcw,
                                                   const float* __restrict__ fcb,
                                                   float* __restrict__ out) {
    __shared__ float ta[2][64];
    __shared__ float r0[64], r1[64];
    __shared__ float sc[2];
    int n = blockIdx.x, o = threadIdx.x;

    float m0 = 0.f, m1 = 0.f;
    const float* p0 = g_o1a + (size_t)n * 512 + o;
    const float* p1 = g_o1b + (size_t)n * 512 + o;
#pragma unroll
    for (int h = 0; h < 8; h++) { m0 += p0[h * 64]; m1 += p1[h * 64]; }
    m0 *= 0.125f; m1 *= 0.125f;
    ta[0][o] = m0; ta[1][o] = m1;
    __syncthreads();

    float amo = am[o];
    float fa = g_fa[o];
    {
        float acc0 = fa, acc1 = fa;
        for (int d = 0; d < 64; d++) {
            float w = aw2[d * 64 + o];
            acc0 += ta[0][d] * w;
            acc1 += ta[1][d] * w;
        }
        r0[o] = tanhf(acc0) * amo;
        r1[o] = tanhf(acc1) * amo;
    }
    __syncthreads();
    if (o == 0) {
        float s0 = 0.f, s1 = 0.f;
        for (int d = 0; d < 64; d++) { s0 += r0[d]; s1 += r1[d]; }
        sc[0] = s0; sc[1] = s1;
    }
    __syncthreads();
    float mx = fmaxf(sc[0], sc[1]);
    float b0 = __expf(sc[0] - mx), b1 = __expf(sc[1] - mx);
    float inv = 1.f / (b0 + b1);
    b0 *= inv; b1 *= inv;
    float fus = b0 * m0 + b1 * m1;

    r0[o] = m0 * fcw[o * 2 + 0] + m1 * fcw[(64 + o) * 2 + 0] + fus * fcw[(128 + o) * 2 + 0];
    r1[o] = m0 * fcw[o * 2 + 1] + m1 * fcw[(64 + o) * 2 + 1] + fus * fcw[(128 + o) * 2 + 1];
    __syncthreads();
    if (o == 0) {
        float l0 = fcb[0], l1 = fcb[1];
        for (int d = 0; d < 64; d++) { l0 += r0[d]; l1 += r1[d]; }
        float m = fmaxf(l0, l1);
        float lse = m + logf(__expf(l0 - m) + __expf(l1 - m));
        out[n * 2 + 0] = l0 - lse;
        out[n * 2 + 1] = l1 - lse;
    }
}

// ---------------- launcher: fork/join two per-type chains ----------------
extern "C" void kernel_launch(void* const* d_in, const int* in_sizes, int n_in,
                              void* d_out, int out_size)
{
    const float* hemb[2] = {(const float*)d_in[0], (const float*)d_in[1]};
    const float* W[2]    = {(const float*)d_in[2], (const float*)d_in[3]};
    const float* gw[2][2]    = {{(const float*)d_in[4],  (const float*)d_in[7]},
                                {(const float*)d_in[10], (const float*)d_in[13]}};
    const float* gasrc[2][2] = {{(const float*)d_in[5],  (const float*)d_in[8]},
                                {(const float*)d_in[11], (const float*)d_in[14]}};
    const float* gatrg[2][2] = {{(const float*)d_in[6],  (const float*)d_in[9]},
                                {(const float*)d_in[12], (const float*)d_in[15]}};
    const float* aw1 = (const float*)d_in[16];
    const float* aw2 = (const float*)d_in[17];
    const float* am  = (const float*)d_in[18];
    const float* fcw = (const float*)d_in[19];
    const float* fcb = (const float*)d_in[20];
    const int* edge[2] = {(const int*)d_in[21], (const int*)d_in[22]};

    uint32_t *trans[2], *Bp[2], *hp[2], *x0[2];
    float *o1[2], *sArr[2], *tArr[2];
    int *csr[2], *rowptr[2];
    {
        uint32_t* ub;
        cudaGetSymbolAddress((void**)&ub, g_trans); trans[0] = ub; trans[1] = ub + NN * FUNI / 2;
        cudaGetSymbolAddress((void**)&ub, g_Bpd);   Bp[0] = ub;    Bp[1] = ub + 512 * 256;
        cudaGetSymbolAddress((void**)&ub, g_hpd);   hp[0] = ub;    hp[1] = ub + NN * HF / 2;
        cudaGetSymbolAddress((void**)&ub, g_x0d);   x0[0] = ub;    x0[1] = ub + NN * HF / 2;
        float* fb;
        cudaGetSymbolAddress((void**)&fb, g_o1a);   o1[0] = fb;
        cudaGetSymbolAddress((void**)&fb, g_o1b);   o1[1] = fb;
        cudaGetSymbolAddress((void**)&fb, g_sd);    sArr[0] = fb;  sArr[1] = fb + NN * HH;
        cudaGetSymbolAddress((void**)&fb, g_td);    tArr[0] = fb;  tArr[1] = fb + NN * HH;
        int* ib;
        cudaGetSymbolAddress((void**)&ib, g_csr);    csr[0] = ib;    csr[1] = ib + EE;
        cudaGetSymbolAddress((void**)&ib, g_rowptr); rowptr[0] = ib; rowptr[1] = ib + (NN + 1);
    }

    cudaFuncSetAttribute(gemm_bf16, cudaFuncAttributeMaxDynamicSharedMemorySize, SMEM_GEMM);

    const dim3 gridT(FUNI / 128, (NN + 127) / 128);
    const dim3 gridH(HF / 128,  (NN + 127) / 128);
    const int gatherBlocks = (NN * 32 + 255) / 256;   // one warp per node

    cudaStream_t str[2] = {(cudaStream_t)0, g_hx.s1};

    // fork: s1 joins the capture after the (empty) prologue on the capture stream
    cudaEventRecord(g_hx.e0, str[0]);
    cudaStreamWaitEvent(str[1], g_hx.e0, 0);

    for (int t = 0; t < 2; t++) {
        cudaStream_t s = str[t];
        const int* src = edge[t];
        const int* trg = edge[t] + EE;

        // CSR build
        zero_cnt<<<(NN + 255) / 256, 256, 0, s>>>(t);
        hist_kernel<<<(EE + 255) / 256, 256, 0, s>>>(trg, t);
        scan_kernel<<<1, 1024, 0, s>>>(t);
        fill_kernel<<<(EE + 255) / 256, 256, 0, s>>>(src, trg, t);

        // pack emb -> hp[t] (free until layer-0 GEMM overwrites it)
        pack_bf16_k<<<(NN * 64 + 255) / 256, 256, 0, s>>>(hp[t], hemb[t], NN * 64);

        // trans GEMM
        transpose_pack<<<(256 * 64 + 255) / 256, 256, 0, s>>>(Bp[t], W[t]);
        gemm_bf16<<<gridT, 256, SMEM_GEMM, s>>>(hp[t], Bp[t], trans[t], NN, 128, FUNI);

        // layer 0 (fin = 256); ELU + bf16 pack fused into gather
        repack_pack<<<(512 * 128 + 255) / 256, 256, 0, s>>>(Bp[t], gw[t][0], FUNI);
        gemm_bf16<<<gridH, 256, SMEM_GEMM, s>>>(trans[t], Bp[t], hp[t], NN, FUNI, HF);
        st_kernel<<<(NN * HH + 255) / 256, 256, 0, s>>>(hp[t], gasrc[t][0], gatrg[t][0], sArr[t], tArr[t]);
        gather_agg<<<gatherBlocks, 256, 0, s>>>(csr[t], rowptr[t], hp[t], sArr[t], tArr[t], x0[t], 1);

        // layer 1 (fin = 512), fp32 output for the final stage
        repack_pack<<<(512 * 256 + 255) / 256, 256, 0, s>>>(Bp[t], gw[t][1], HF);
        gemm_bf16<<<gridH, 256, SMEM_GEMM, s>>>(x0[t], Bp[t], hp[t], NN, HF, HF);
        st_kernel<<<(NN * HH + 255) / 256, 256, 0, s>>>(hp[t], gasrc[t][1], gatrg[t][1], sArr[t], tArr[t]);
        gather_agg<<<gatherBlocks, 256, 0, s>>>(csr[t], rowptr[t], hp[t], sArr[t], tArr[t], o1[t], 0);
    }

    // join: capture stream waits for the type-1 chain
    cudaEventRecord(g_hx.e1, str[1]);
    cudaStreamWaitEvent(str[0], g_hx.e1, 0);

    fa_kernel<<<1, 64, 0, str[0]>>>(trans[1], aw1);
    final_kernel<<<NN, 64, 0, str[0]>>>(aw2, am, fcw, fcb, (float*)d_out);
}

// round 14
// speedup vs baseline: 2.5637x; 1.3342x over previous
#include <cuda_runtime.h>
#include <cstdint>
#include <cstddef>

#define NN   20000
#define EE   320000
#define HH   8
#define FUNI 256
#define FOUT 64
#define HF   512   // H*FOUT

// ---------------- scratch (device globals; no runtime allocation) ----------------
__device__ uint32_t g_trans[2][NN * FUNI / 2];   // bf16x2
__device__ uint32_t g_Bpd[2][512 * 256];         // repacked weights, bf16x2
__device__ uint32_t g_hpd[2][NN * HF / 2];       // projected features (bf16); packed emb early
__device__ uint32_t g_x0d[2][NN * HF / 2];       // layer-0 aggregated (bf16, ELU'd)
__device__ float g_o1a[NN * HF];                 // layer-1 aggregated, type 0 (fp32)
__device__ float g_o1b[NN * HF];                 // layer-1 aggregated, type 1 (fp32)
__device__ float g_sd[2][NN * HH];
__device__ float g_td[2][NN * HH];
__device__ float g_fa[FOUT];

// CSR scratch (per type)
__device__ int g_cntd[2][NN];
__device__ int g_rowptr[2][NN + 1];
__device__ int g_woffd[2][NN];
__device__ int g_csr[2][EE];

// ---------------- static stream/event context (created at load, NOT during capture) ----
struct HxCtx {
    cudaStream_t s1, s2, s3;        // s1: type-1 chain; s2/s3: CSR builds
    cudaEvent_t e0, e1, ec0, ec1;
    HxCtx() {
        cudaStreamCreateWithFlags(&s1, cudaStreamNonBlocking);
        cudaStreamCreateWithFlags(&s2, cudaStreamNonBlocking);
        cudaStreamCreateWithFlags(&s3, cudaStreamNonBlocking);
        cudaEventCreateWithFlags(&e0, cudaEventDisableTiming);
        cudaEventCreateWithFlags(&e1, cudaEventDisableTiming);
        cudaEventCreateWithFlags(&ec0, cudaEventDisableTiming);
        cudaEventCreateWithFlags(&ec1, cudaEventDisableTiming);
    }
};
static HxCtx g_hx;

// ---------------- helpers ----------------
__device__ __forceinline__ uint32_t smem_to_u32(const void* p) {
    uint32_t a;
    asm("{ .reg .u64 t; cvta.to.shared.u64 t, %1; cvt.u32.u64 %0, t; }" : "=r"(a) : "l"(p));
    return a;
}
__device__ __forceinline__ void cp16(uint32_t saddr, const void* g) {
    asm volatile("cp.async.cg.shared.global [%0], [%1], 16;" :: "r"(saddr), "l"(g));
}
__device__ __forceinline__ void sts_zero16(uint32_t saddr) {
    asm volatile("st.shared.v4.b32 [%0], {%1,%1,%1,%1};" :: "r"(saddr), "r"(0u));
}
#define CP_COMMIT() asm volatile("cp.async.commit_group;" ::: "memory")
#define CP_WAIT2()  asm volatile("cp.async.wait_group 2;" ::: "memory")

__device__ __forceinline__ uint32_t pack_bf16x2(float a, float b) {
    uint32_t r;
    asm("cvt.rn.bf16x2.f32 %0, %1, %2;" : "=r"(r) : "f"(b), "f"(a));
    return r;
}
__device__ __forceinline__ float bf_lo(uint32_t u) { return __uint_as_float(u << 16); }
__device__ __forceinline__ float bf_hi(uint32_t u) { return __uint_as_float(u & 0xffff0000u); }
__device__ __forceinline__ float eluf(float x) { return x > 0.f ? x : (__expf(x) - 1.f); }

__device__ __forceinline__ void mma_bf16(float* c, const uint32_t* a, const uint32_t* b) {
    asm volatile("mma.sync.aligned.m16n8k16.row.col.f32.bf16.bf16.f32 "
                 "{%0,%1,%2,%3}, {%4,%5,%6,%7}, {%8,%9}, {%0,%1,%2,%3};"
                 : "+f"(c[0]), "+f"(c[1]), "+f"(c[2]), "+f"(c[3])
                 : "r"(a[0]), "r"(a[1]), "r"(a[2]), "r"(a[3]), "r"(b[0]), "r"(b[1]));
}

// ---------------- bf16 mma GEMM + fused s/t epilogue ----------------
// C[M,NC] = A[M,K] @ Bt[NC,K]^T, bf16x2-packed.
// If sOut != nullptr: each warp (covering one 64-col head span) also computes
// s[row, head] = Crow_head · asrc[head], t likewise, from the fp32 accumulators.
#define STAGES  3
#define STRIDEU 20
#define TILEU   (128 * STRIDEU)
#define STAGEU  (2 * TILEU)
#define SMEM_GEMM (STAGES * STAGEU * 4)    // 61440 bytes

__global__ __launch_bounds__(256, 2)
void gemm_bf16(const uint32_t* __restrict__ A, const uint32_t* __restrict__ Bt,
               uint32_t* __restrict__ C, int M, int K, int NC,
               const float* __restrict__ asrc, const float* __restrict__ atrg,
               float* __restrict__ sOut, float* __restrict__ tOut)
{
    const uint32_t FULL = 0xffffffffu;
    extern __shared__ uint32_t smu[];
    const int tid  = threadIdx.x;
    const int wid  = tid >> 5, lane = tid & 31;
    const int g    = lane >> 2, t = lane & 3;
    const int bm   = blockIdx.y << 7, bn = blockIdx.x << 7;
    const int m0   = (wid >> 1) * 32;
    const int n0   = (wid & 1) * 64;
    const int KU   = K >> 1;
    const int NCU  = NC >> 1;
    const int P    = K >> 5;

    const uint32_t sb = smem_to_u32(smu);
    const int lrow = tid >> 2;
    const int lc4  = tid & 3;

    float acc[2][8][4];
#pragma unroll
    for (int i = 0; i < 2; i++)
#pragma unroll
        for (int j = 0; j < 8; j++)
#pragma unroll
            for (int q = 0; q < 4; q++) acc[i][j][q] = 0.f;

#pragma unroll
    for (int s = 0; s < STAGES; s++) {
        uint32_t stb = sb + s * STAGEU * 4;
#pragma unroll
        for (int j = 0; j < 2; j++) {
            int row = lrow + j * 64;
            uint32_t sa = stb + (row * STRIDEU + lc4 * 4) * 4;
            int ar = bm + row;
            if (ar < M) cp16(sa, A + (size_t)ar * KU + s * 16 + lc4 * 4);
            else        sts_zero16(sa);
            uint32_t sbB = stb + TILEU * 4 + (row * STRIDEU + lc4 * 4) * 4;
            cp16(sbB, Bt + (size_t)(bn + row) * KU + s * 16 + lc4 * 4);
        }
        CP_COMMIT();
    }

    for (int p = 0; p < P; p++) {
        const int slot = p % STAGES;
        CP_WAIT2();
        __syncthreads();
        const uint32_t* As = smu + slot * STAGEU;
        const uint32_t* Bs = As + TILEU;

#pragma unroll
        for (int ks = 0; ks < 2; ks++) {
            uint32_t a[2][4], b[8][2];
#pragma unroll
            for (int i = 0; i < 2; i++) {
                int base = (m0 + i * 16 + g) * STRIDEU + ks * 8 + t;
                a[i][0] = As[base];
                a[i][1] = As[base + 8 * STRIDEU];
                a[i][2] = As[base + 4];
                a[i][3] = As[base + 8 * STRIDEU + 4];
            }
#pragma unroll
            for (int j = 0; j < 8; j++) {
                int bb = (n0 + j * 8 + g) * STRIDEU + ks * 8 + t;
                b[j][0] = Bs[bb];
                b[j][1] = Bs[bb + 4];
            }
#pragma unroll
            for (int i = 0; i < 2; i++)
#pragma unroll
                for (int j = 0; j < 8; j++)
                    mma_bf16(acc[i][j], a[i], b[j]);
        }
        __syncthreads();

        int np = p + STAGES;
        if (np < P) {
            uint32_t stb = sb + slot * STAGEU * 4;
#pragma unroll
            for (int j = 0; j < 2; j++) {
                int row = lrow + j * 64;
                uint32_t sa = stb + (row * STRIDEU + lc4 * 4) * 4;
                int ar = bm + row;
                if (ar < M) cp16(sa, A + (size_t)ar * KU + np * 16 + lc4 * 4);
                else        sts_zero16(sa);
                uint32_t sbB = stb + TILEU * 4 + (row * STRIDEU + lc4 * 4) * 4;
                cp16(sbB, Bt + (size_t)(bn + row) * KU + np * 16 + lc4 * 4);
            }
        }
        CP_COMMIT();
    }

    // ---- epilogue 1: store bf16x2 C ----
#pragma unroll
    for (int i = 0; i < 2; i++) {
        int r0 = bm + m0 + i * 16 + g;
#pragma unroll
        for (int j = 0; j < 8; j++) {
            int colu = ((bn + n0 + j * 8) >> 1) + t;
            if (r0 < M)
                C[(size_t)r0 * NCU + colu] = pack_bf16x2(acc[i][j][0], acc[i][j][1]);
            if (r0 + 8 < M)
                C[(size_t)(r0 + 8) * NCU + colu] = pack_bf16x2(acc[i][j][2], acc[i][j][3]);
        }
    }

    // ---- epilogue 2: fused s/t projection (warp's 64 cols = exactly one head) ----
    if (sOut != nullptr) {
        int hh = (bn + n0) >> 6;                  // head index for this warp
        const float* av = asrc + hh * 64;
        const float* bv = atrg + hh * 64;
        float aw[16], bw[16];
#pragma unroll
        for (int j = 0; j < 8; j++) {
            int c0 = j * 8 + 2 * t;
            aw[2 * j] = av[c0];     aw[2 * j + 1] = av[c0 + 1];
            bw[2 * j] = bv[c0];     bw[2 * j + 1] = bv[c0 + 1];
        }
#pragma unroll
        for (int i = 0; i < 2; i++) {
#pragma unroll
            for (int half = 0; half < 2; half++) {
                float ss = 0.f, ts = 0.f;
#pragma unroll
                for (int j = 0; j < 8; j++) {
                    float c0 = acc[i][j][half * 2 + 0];
                    float c1 = acc[i][j][half * 2 + 1];
                    ss += c0 * aw[2 * j] + c1 * aw[2 * j + 1];
                    ts += c0 * bw[2 * j] + c1 * bw[2 * j + 1];
                }
                ss += __shfl_xor_sync(FULL, ss, 1);
                ss += __shfl_xor_sync(FULL, ss, 2);
                ts += __shfl_xor_sync(FULL, ts, 1);
                ts += __shfl_xor_sync(FULL, ts, 2);
                int row = bm + m0 + i * 16 + g + half * 8;
                if (t == 0 && row < M) {
                    sOut[row * 8 + hh] = ss;
                    tOut[row * 8 + hh] = ts;
                }
            }
        }
    }
}

// ---------------- CSR build (per type t) ----------------
__global__ void zero_cnt(int t) {
    int i = blockIdx.x * blockDim.x + threadIdx.x;
    if (i < NN) g_cntd[t][i] = 0;
}
__global__ void hist_kernel(const int* __restrict__ trg, int t) {
    int e = blockIdx.x * blockDim.x + threadIdx.x;
    if (e < EE) atomicAdd(&g_cntd[t][trg[e]], 1);
}
#define SCAN_CH 20
__global__ __launch_bounds__(1024) void scan_kernel(int t) {
    __shared__ int part[1024];
    int tid = threadIdx.x;
    int base = tid * SCAN_CH;
    int loc[SCAN_CH];
    int s = 0;
#pragma unroll
    for (int i = 0; i < SCAN_CH; i++) {
        int idx = base + i;
        int v = (idx < NN) ? g_cntd[t][idx] : 0;
        loc[i] = s;
        s += v;
    }
    part[tid] = s;
    __syncthreads();
    for (int d = 1; d < 1024; d <<= 1) {
        int v = (tid >= d) ? part[tid - d] : 0;
        __syncthreads();
        part[tid] += v;
        __syncthreads();
    }
    int excl = part[tid] - s;
#pragma unroll
    for (int i = 0; i < SCAN_CH; i++) {
        int idx = base + i;
        if (idx < NN) {
            int v = loc[i] + excl;
            g_rowptr[t][idx] = v;
            g_woffd[t][idx] = v;
        }
    }
    if (tid == 1023) g_rowptr[t][NN] = part[1023];
}
__global__ void fill_kernel(const int* __restrict__ src, const int* __restrict__ trg, int t) {
    int e = blockIdx.x * blockDim.x + threadIdx.x;
    if (e >= EE) return;
    int p = atomicAdd(&g_woffd[t][trg[e]], 1);
    g_csr[t][p] = src[e];
}

// ---------------- gather-aggregate: one warp per node, 4 edges per step ----------------
__global__ __launch_bounds__(256) void gather_agg(const int* __restrict__ csr,
                                                  const int* __restrict__ rowptr,
                                                  const uint32_t* __restrict__ hp,
                                                  const float* __restrict__ sArr,
                                                  const float* __restrict__ tArr,
                                                  void* __restrict__ outp,
                                                  int mode)
{
    const uint32_t FULL = 0xffffffffu;
    int node = (blockIdx.x * 256 + threadIdx.x) >> 5;
    int lane = threadIdx.x & 31;
    if (node >= NN) return;
    int beg = rowptr[node], end = rowptr[node + 1];

    const int h = lane & 7;
    const int eg = lane >> 3;
    float tval = tArr[node * 8 + h];

    float dsum = 0.f;
    float acc[2][8];
#pragma unroll
    for (int j = 0; j < 2; j++)
#pragma unroll
        for (int k = 0; k < 8; k++) acc[j][k] = 0.f;

    for (int base = beg; base < end; base += 32) {
        int nrem = end - base; if (nrem > 32) nrem = 32;
        int sv = (base + lane < end) ? csr[base + lane] : 0;

        for (int i4 = 0; i4 < nrem; i4 += 4) {
            int myEdge = i4 + eg;
            int srcE = __shfl_sync(FULL, sv, myEdge & 31);
            float ex = 0.f;
            if (myEdge < nrem) {
                float v = sArr[srcE * 8 + h] + tval;
                ex = __expf(fmaxf(v, 0.2f * v));   // global max-shift cancels in alpha
                dsum += ex;
            }
#pragma unroll
            for (int i = 0; i < 4; i++) {
                int srcp = __shfl_sync(FULL, sv, (i4 + i) & 31);
                const uint4* hv = (const uint4*)(hp + (size_t)srcp * 256);
#pragma unroll
                for (int j = 0; j < 2; j++) {
                    int c = lane + 32 * j;
                    float al = __shfl_sync(FULL, ex, (i << 3) | (c >> 3));
                    uint4 v = hv[c];
                    acc[j][0] += al * bf_lo(v.x); acc[j][1] += al * bf_hi(v.x);
                    acc[j][2] += al * bf_lo(v.y); acc[j][3] += al * bf_hi(v.y);
                    acc[j][4] += al * bf_lo(v.z); acc[j][5] += al * bf_hi(v.z);
                    acc[j][6] += al * bf_lo(v.w); acc[j][7] += al * bf_hi(v.w);
                }
            }
        }
    }

    dsum += __shfl_xor_sync(FULL, dsum, 8);
    dsum += __shfl_xor_sync(FULL, dsum, 16);

#pragma unroll
    for (int j = 0; j < 2; j++) {
        int c = lane + 32 * j;
        float dn = __shfl_sync(FULL, dsum, c >> 3) + 1e-16f;
        float inv = 1.f / dn;
        float v0 = acc[j][0] * inv, v1 = acc[j][1] * inv;
        float v2 = acc[j][2] * inv, v3 = acc[j][3] * inv;
        float v4 = acc[j][4] * inv, v5 = acc[j][5] * inv;
        float v6 = acc[j][6] * inv, v7 = acc[j][7] * inv;
        if (mode == 0) {
            float* out = (float*)outp;
            float4* ob = (float4*)(out + (size_t)node * 512 + c * 8);
            ob[0] = make_float4(v0, v1, v2, v3);
            ob[1] = make_float4(v4, v5, v6, v7);
        } else {
            uint32_t* out = (uint32_t*)outp;
            uint4 pk;
            pk.x = pack_bf16x2(eluf(v0), eluf(v1));
            pk.y = pack_bf16x2(eluf(v2), eluf(v3));
            pk.z = pack_bf16x2(eluf(v4), eluf(v5));
            pk.w = pack_bf16x2(eluf(v6), eluf(v7));
            ((uint4*)(out + (size_t)node * 256))[c] = pk;
        }
    }
}

// ---------------- prep kernels ----------------
__global__ void pack_bf16_k(uint32_t* __restrict__ dst, const float* __restrict__ src, int n2) {
    int i = blockIdx.x * blockDim.x + threadIdx.x;
    if (i < n2) dst[i] = pack_bf16x2(src[2 * i], src[2 * i + 1]);
}
__global__ void transpose_pack(uint32_t* __restrict__ Wt, const float* __restrict__ W) {
    int i = blockIdx.x * blockDim.x + threadIdx.x;
    if (i >= 256 * 64) return;
    int n = i >> 6, ku = i & 63;
    Wt[i] = pack_bf16x2(W[(2 * ku) * 256 + n], W[(2 * ku + 1) * 256 + n]);
}
__global__ void repack_pack(uint32_t* __restrict__ Bt, const float* __restrict__ w, int fin) {
    int finu = fin >> 1;
    int i = blockIdx.x * blockDim.x + threadIdx.x;
    if (i >= 512 * finu) return;
    int n = i / finu, ku = i % finu;
    int h = n >> 6, o = n & 63;
    int k0 = 2 * ku;
    Bt[i] = pack_bf16x2(w[((size_t)(h * fin + k0) << 6) + o],
                        w[((size_t)(h * fin + k0 + 1) << 6) + o]);
}

__global__ void fa_kernel(const uint32_t* __restrict__ trans1, const float* __restrict__ aw1) {
    int o = threadIdx.x;
    float acc = 0.f;
    for (int f2 = 0; f2 < 128; f2++) {
        uint32_t u = trans1[f2];
        acc += bf_lo(u) * aw1[(2 * f2) * 64 + o] + bf_hi(u) * aw1[(2 * f2 + 1) * 64 + o];
    }
    g_fa[o] = acc;
}

__global__ __launch_bounds__(64) void final_kernel(const float* __restrict__ aw2,
                                                   const float* __restrict__ am,
                                                   const float* __restrict__ fcw,
                                                   const float* __restrict__ fcb,
                                                   float* __restrict__ out) {
    __shared__ float ta[2][64];
    __shared__ float r0[64], r1[64];
    __shared__ float sc[2];
    int n = blockIdx.x, o = threadIdx.x;

    float m0 = 0.f, m1 = 0.f;
    const float* p0 = g_o1a + (size_t)n * 512 + o;
    const float* p1 = g_o1b + (size_t)n * 512 + o;
#pragma unroll
    for (int h = 0; h < 8; h++) { m0 += p0[h * 64]; m1 += p1[h * 64]; }
    m0 *= 0.125f; m1 *= 0.125f;
    ta[0][o] = m0; ta[1][o] = m1;
    __syncthreads();

    float amo = am[o];
    float fa = g_fa[o];
    {
        float acc0 = fa, acc1 = fa;
        for (int d = 0; d < 64; d++) {
            float w = aw2[d * 64 + o];
            acc0 += ta[0][d] * w;
            acc1 += ta[1][d] * w;
        }
        r0[o] = tanhf(acc0) * amo;
        r1[o] = tanhf(acc1) * amo;
    }
    __syncthreads();
    if (o == 0) {
        float s0 = 0.f, s1 = 0.f;
        for (int d = 0; d < 64; d++) { s0 += r0[d]; s1 += r1[d]; }
        sc[0] = s0; sc[1] = s1;
    }
    __syncthreads();
    float mx = fmaxf(sc[0], sc[1]);
    float b0 = __expf(sc[0] - mx), b1 = __expf(sc[1] - mx);
    float inv = 1.f / (b0 + b1);
    b0 *= inv; b1 *= inv;
    float fus = b0 * m0 + b1 * m1;

    r0[o] = m0 * fcw[o * 2 + 0] + m1 * fcw[(64 + o) * 2 + 0] + fus * fcw[(128 + o) * 2 + 0];
    r1[o] = m0 * fcw[o * 2 + 1] + m1 * fcw[(64 + o) * 2 + 1] + fus * fcw[(128 + o) * 2 + 1];
    __syncthreads();
    if (o == 0) {
        float l0 = fcb[0], l1 = fcb[1];
        for (int d = 0; d < 64; d++) { l0 += r0[d]; l1 += r1[d]; }
        float m = fmaxf(l0, l1);
        float lse = m + logf(__expf(l0 - m) + __expf(l1 - m));
        out[n * 2 + 0] = l0 - lse;
        out[n * 2 + 1] = l1 - lse;
    }
}

// ---------------- launcher: fork/join, CSR on side streams ----------------
extern "C" void kernel_launch(void* const* d_in, const int* in_sizes, int n_in,
                              void* d_out, int out_size)
{
    const float* hemb[2] = {(const float*)d_in[0], (const float*)d_in[1]};
    const float* W[2]    = {(const float*)d_in[2], (const float*)d_in[3]};
    const float* gw[2][2]    = {{(const float*)d_in[4],  (const float*)d_in[7]},
                                {(const float*)d_in[10], (const float*)d_in[13]}};
    const float* gasrc[2][2] = {{(const float*)d_in[5],  (const float*)d_in[8]},
                                {(const float*)d_in[11], (const float*)d_in[14]}};
    const float* gatrg[2][2] = {{(const float*)d_in[6],  (const float*)d_in[9]},
                                {(const float*)d_in[12], (const float*)d_in[15]}};
    const float* aw1 = (const float*)d_in[16];
    const float* aw2 = (const float*)d_in[17];
    const float* am  = (const float*)d_in[18];
    const float* fcw = (const float*)d_in[19];
    const float* fcb = (const float*)d_in[20];
    const int* edge[2] = {(const int*)d_in[21], (const int*)d_in[22]};

    uint32_t *trans[2], *Bp[2], *hp[2], *x0[2];
    float *o1[2], *sArr[2], *tArr[2];
    int *csr[2], *rowptr[2];
    {
        uint32_t* ub;
        cudaGetSymbolAddress((void**)&ub, g_trans); trans[0] = ub; trans[1] = ub + NN * FUNI / 2;
        cudaGetSymbolAddress((void**)&ub, g_Bpd);   Bp[0] = ub;    Bp[1] = ub + 512 * 256;
        cudaGetSymbolAddress((void**)&ub, g_hpd);   hp[0] = ub;    hp[1] = ub + NN * HF / 2;
        cudaGetSymbolAddress((void**)&ub, g_x0d);   x0[0] = ub;    x0[1] = ub + NN * HF / 2;
        float* fb;
        cudaGetSymbolAddress((void**)&fb, g_o1a);   o1[0] = fb;
        cudaGetSymbolAddress((void**)&fb, g_o1b);   o1[1] = fb;
        cudaGetSymbolAddress((void**)&fb, g_sd);    sArr[0] = fb;  sArr[1] = fb + NN * HH;
        cudaGetSymbolAddress((void**)&fb, g_td);    tArr[0] = fb;  tArr[1] = fb + NN * HH;
        int* ib;
        cudaGetSymbolAddress((void**)&ib, g_csr);    csr[0] = ib;    csr[1] = ib + EE;
        cudaGetSymbolAddress((void**)&ib, g_rowptr); rowptr[0] = ib; rowptr[1] = ib + (NN + 1);
    }

    cudaFuncSetAttribute(gemm_bf16, cudaFuncAttributeMaxDynamicSharedMemorySize, SMEM_GEMM);

    const dim3 gridT(FUNI / 128, (NN + 127) / 128);
    const dim3 gridH(HF / 128,  (NN + 127) / 128);
    const int gatherBlocks = (NN * 32 + 255) / 256;

    cudaStream_t chain[2] = {(cudaStream_t)0, g_hx.s1};
    cudaStream_t csrS[2]  = {g_hx.s2, g_hx.s3};
    cudaEvent_t  csrE[2]  = {g_hx.ec0, g_hx.ec1};

    // fork from the capture stream
    cudaEventRecord(g_hx.e0, chain[0]);
    cudaStreamWaitEvent(chain[1], g_hx.e0, 0);
    cudaStreamWaitEvent(csrS[0], g_hx.e0, 0);
    cudaStreamWaitEvent(csrS[1], g_hx.e0, 0);

    // CSR builds on side streams (overlap the GEMM prefix)
    for (int t = 0; t < 2; t++) {
        const int* src = edge[t];
        const int* trg = edge[t] + EE;
        zero_cnt<<<(NN + 255) / 256, 256, 0, csrS[t]>>>(t);
        hist_kernel<<<(EE + 255) / 256, 256, 0, csrS[t]>>>(trg, t);
        scan_kernel<<<1, 1024, 0, csrS[t]>>>(t);
        fill_kernel<<<(EE + 255) / 256, 256, 0, csrS[t]>>>(src, trg, t);
        cudaEventRecord(csrE[t], csrS[t]);
    }

    for (int t = 0; t < 2; t++) {
        cudaStream_t s = chain[t];

        // pack emb -> hp[t]
        pack_bf16_k<<<(NN * 64 + 255) / 256, 256, 0, s>>>(hp[t], hemb[t], NN * 64);

        // trans GEMM (no s/t epilogue)
        transpose_pack<<<(256 * 64 + 255) / 256, 256, 0, s>>>(Bp[t], W[t]);
        gemm_bf16<<<gridT, 256, SMEM_GEMM, s>>>(hp[t], Bp[t], trans[t], NN, 128, FUNI,
                                                nullptr, nullptr, nullptr, nullptr);

        // layer 0 GEMM with fused s/t
        repack_pack<<<(512 * 128 + 255) / 256, 256, 0, s>>>(Bp[t], gw[t][0], FUNI);
        gemm_bf16<<<gridH, 256, SMEM_GEMM, s>>>(trans[t], Bp[t], hp[t], NN, FUNI, HF,
                                                gasrc[t][0], gatrg[t][0], sArr[t], tArr[t]);
        cudaStreamWaitEvent(s, csrE[t], 0);   // CSR must be ready for the gather
        gather_agg<<<gatherBlocks, 256, 0, s>>>(csr[t], rowptr[t], hp[t], sArr[t], tArr[t], x0[t], 1);

        // layer 1 GEMM with fused s/t
        repack_pack<<<(512 * 256 + 255) / 256, 256, 0, s>>>(Bp[t], gw[t][1], HF);
        gemm_bf16<<<gridH, 256, SMEM_GEMM, s>>>(x0[t], Bp[t], hp[t], NN, HF, HF,
                                                gasrc[t][1], gatrg[t][1], sArr[t], tArr[t]);
        gather_agg<<<gatherBlocks, 256, 0, s>>>(csr[t], rowptr[t], hp[t], sArr[t], tArr[t], o1[t], 0);
    }

    // join
    cudaEventRecord(g_hx.e1, chain[1]);
    cudaStreamWaitEvent(chain[0], g_hx.e1, 0);

    fa_kernel<<<1, 64, 0, chain[0]>>>(trans[1], aw1);
    final_kernel<<<NN, 64, 0, chain[0]>>>(aw2, am, fcw, fcb, (float*)d_out);
}

// round 15
// speedup vs baseline: 2.5968x; 1.0129x over previous
#include <cuda_runtime.h>
#include <cstdint>
#include <cstddef>

#define NN   20000
#define EE   320000
#define HH   8
#define FUNI 256
#define FOUT 64
#define HF   512   // H*FOUT

// ---------------- scratch (device globals; no runtime allocation) ----------------
__device__ uint32_t g_trans[2][NN * FUNI / 2];   // bf16x2
__device__ uint32_t g_BpT[2][256 * 64];          // trans weights,  [256][64]  bf16x2
__device__ uint32_t g_Bp0[2][512 * 128];         // layer-0 weights [512][128] bf16x2
__device__ uint32_t g_Bp1[2][512 * 256];         // layer-1 weights [512][256] bf16x2
__device__ uint32_t g_hpd[2][NN * HF / 2];       // projected features (bf16); packed emb early
__device__ uint32_t g_x0d[2][NN * HF / 2];       // layer-0 aggregated (bf16, ELU'd)
__device__ float g_o1a[NN * HF];                 // layer-1 aggregated, type 0 (fp32)
__device__ float g_o1b[NN * HF];                 // layer-1 aggregated, type 1 (fp32)
__device__ float g_sd[2][NN * HH];
__device__ float g_td[2][NN * HH];
__device__ float g_fa[FOUT];

// CSR scratch (per type)
__device__ int g_cntd[2][NN];
__device__ int g_rowptr[2][NN + 1];
__device__ int g_woffd[2][NN];
__device__ int g_csr[2][EE];

// ---------------- static stream/event context (created at load, NOT during capture) ----
struct HxCtx {
    cudaStream_t s1, s2, s3;        // s1: type-1 chain; s2/s3: per-type prep+CSR
    cudaEvent_t e0, e1, ec0, ec1, ep0, ep1;
    HxCtx() {
        cudaStreamCreateWithFlags(&s1, cudaStreamNonBlocking);
        cudaStreamCreateWithFlags(&s2, cudaStreamNonBlocking);
        cudaStreamCreateWithFlags(&s3, cudaStreamNonBlocking);
        cudaEventCreateWithFlags(&e0, cudaEventDisableTiming);
        cudaEventCreateWithFlags(&e1, cudaEventDisableTiming);
        cudaEventCreateWithFlags(&ec0, cudaEventDisableTiming);
        cudaEventCreateWithFlags(&ec1, cudaEventDisableTiming);
        cudaEventCreateWithFlags(&ep0, cudaEventDisableTiming);
        cudaEventCreateWithFlags(&ep1, cudaEventDisableTiming);
    }
};
static HxCtx g_hx;

// ---------------- helpers ----------------
__device__ __forceinline__ uint32_t smem_to_u32(const void* p) {
    uint32_t a;
    asm("{ .reg .u64 t; cvta.to.shared.u64 t, %1; cvt.u32.u64 %0, t; }" : "=r"(a) : "l"(p));
    return a;
}
__device__ __forceinline__ void cp16(uint32_t saddr, const void* g) {
    asm volatile("cp.async.cg.shared.global [%0], [%1], 16;" :: "r"(saddr), "l"(g));
}
__device__ __forceinline__ void sts_zero16(uint32_t saddr) {
    asm volatile("st.shared.v4.b32 [%0], {%1,%1,%1,%1};" :: "r"(saddr), "r"(0u));
}
#define CP_COMMIT() asm volatile("cp.async.commit_group;" ::: "memory")
#define CP_WAIT2()  asm volatile("cp.async.wait_group 2;" ::: "memory")

__device__ __forceinline__ uint32_t pack_bf16x2(float a, float b) {
    uint32_t r;
    asm("cvt.rn.bf16x2.f32 %0, %1, %2;" : "=r"(r) : "f"(b), "f"(a));
    return r;
}
__device__ __forceinline__ float bf_lo(uint32_t u) { return __uint_as_float(u << 16); }
__device__ __forceinline__ float bf_hi(uint32_t u) { return __uint_as_float(u & 0xffff0000u); }
__device__ __forceinline__ float eluf(float x) { return x > 0.f ? x : (__expf(x) - 1.f); }

__device__ __forceinline__ void mma_bf16(float* c, const uint32_t* a, const uint32_t* b) {
    asm volatile("mma.sync.aligned.m16n8k16.row.col.f32.bf16.bf16.f32 "
                 "{%0,%1,%2,%3}, {%4,%5,%6,%7}, {%8,%9}, {%0,%1,%2,%3};"
                 : "+f"(c[0]), "+f"(c[1]), "+f"(c[2]), "+f"(c[3])
                 : "r"(a[0]), "r"(a[1]), "r"(a[2]), "r"(a[3]), "r"(b[0]), "r"(b[1]));
}

// ---------------- bf16 mma GEMM + fused s/t epilogue ----------------
#define STAGES  3
#define STRIDEU 20
#define TILEU   (128 * STRIDEU)
#define STAGEU  (2 * TILEU)
#define SMEM_GEMM (STAGES * STAGEU * 4)    // 61440 bytes

__global__ __launch_bounds__(256, 2)
void gemm_bf16(const uint32_t* __restrict__ A, const uint32_t* __restrict__ Bt,
               uint32_t* __restrict__ C, int M, int K, int NC,
               const float* __restrict__ asrc, const float* __restrict__ atrg,
               float* __restrict__ sOut, float* __restrict__ tOut)
{
    const uint32_t FULL = 0xffffffffu;
    extern __shared__ uint32_t smu[];
    const int tid  = threadIdx.x;
    const int wid  = tid >> 5, lane = tid & 31;
    const int g    = lane >> 2, t = lane & 3;
    const int bm   = blockIdx.y << 7, bn = blockIdx.x << 7;
    const int m0   = (wid >> 1) * 32;
    const int n0   = (wid & 1) * 64;
    const int KU   = K >> 1;
    const int NCU  = NC >> 1;
    const int P    = K >> 5;

    const uint32_t sb = smem_to_u32(smu);
    const int lrow = tid >> 2;
    const int lc4  = tid & 3;

    float acc[2][8][4];
#pragma unroll
    for (int i = 0; i < 2; i++)
#pragma unroll
        for (int j = 0; j < 8; j++)
#pragma unroll
            for (int q = 0; q < 4; q++) acc[i][j][q] = 0.f;

#pragma unroll
    for (int s = 0; s < STAGES; s++) {
        uint32_t stb = sb + s * STAGEU * 4;
#pragma unroll
        for (int j = 0; j < 2; j++) {
            int row = lrow + j * 64;
            uint32_t sa = stb + (row * STRIDEU + lc4 * 4) * 4;
            int ar = bm + row;
            if (ar < M) cp16(sa, A + (size_t)ar * KU + s * 16 + lc4 * 4);
            else        sts_zero16(sa);
            uint32_t sbB = stb + TILEU * 4 + (row * STRIDEU + lc4 * 4) * 4;
            cp16(sbB, Bt + (size_t)(bn + row) * KU + s * 16 + lc4 * 4);
        }
        CP_COMMIT();
    }

    for (int p = 0; p < P; p++) {
        const int slot = p % STAGES;
        CP_WAIT2();
        __syncthreads();
        const uint32_t* As = smu + slot * STAGEU;
        const uint32_t* Bs = As + TILEU;

#pragma unroll
        for (int ks = 0; ks < 2; ks++) {
            uint32_t a[2][4], b[8][2];
#pragma unroll
            for (int i = 0; i < 2; i++) {
                int base = (m0 + i * 16 + g) * STRIDEU + ks * 8 + t;
                a[i][0] = As[base];
                a[i][1] = As[base + 8 * STRIDEU];
                a[i][2] = As[base + 4];
                a[i][3] = As[base + 8 * STRIDEU + 4];
            }
#pragma unroll
            for (int j = 0; j < 8; j++) {
                int bb = (n0 + j * 8 + g) * STRIDEU + ks * 8 + t;
                b[j][0] = Bs[bb];
                b[j][1] = Bs[bb + 4];
            }
#pragma unroll
            for (int i = 0; i < 2; i++)
#pragma unroll
                for (int j = 0; j < 8; j++)
                    mma_bf16(acc[i][j], a[i], b[j]);
        }
        __syncthreads();

        int np = p + STAGES;
        if (np < P) {
            uint32_t stb = sb + slot * STAGEU * 4;
#pragma unroll
            for (int j = 0; j < 2; j++) {
                int row = lrow + j * 64;
                uint32_t sa = stb + (row * STRIDEU + lc4 * 4) * 4;
                int ar = bm + row;
                if (ar < M) cp16(sa, A + (size_t)ar * KU + np * 16 + lc4 * 4);
                else        sts_zero16(sa);
                uint32_t sbB = stb + TILEU * 4 + (row * STRIDEU + lc4 * 4) * 4;
                cp16(sbB, Bt + (size_t)(bn + row) * KU + np * 16 + lc4 * 4);
            }
        }
        CP_COMMIT();
    }

    // ---- epilogue 1: store bf16x2 C ----
#pragma unroll
    for (int i = 0; i < 2; i++) {
        int r0 = bm + m0 + i * 16 + g;
#pragma unroll
        for (int j = 0; j < 8; j++) {
            int colu = ((bn + n0 + j * 8) >> 1) + t;
            if (r0 < M)
                C[(size_t)r0 * NCU + colu] = pack_bf16x2(acc[i][j][0], acc[i][j][1]);
            if (r0 + 8 < M)
                C[(size_t)(r0 + 8) * NCU + colu] = pack_bf16x2(acc[i][j][2], acc[i][j][3]);
        }
    }

    // ---- epilogue 2: fused s/t projection (warp's 64 cols = exactly one head) ----
    if (sOut != nullptr) {
        int hh = (bn + n0) >> 6;
        const float* av = asrc + hh * 64;
        const float* bv = atrg + hh * 64;
        float aw[16], bw[16];
#pragma unroll
        for (int j = 0; j < 8; j++) {
            int c0 = j * 8 + 2 * t;
            aw[2 * j] = av[c0];     aw[2 * j + 1] = av[c0 + 1];
            bw[2 * j] = bv[c0];     bw[2 * j + 1] = bv[c0 + 1];
        }
#pragma unroll
        for (int i = 0; i < 2; i++) {
#pragma unroll
            for (int half = 0; half < 2; half++) {
                float ss = 0.f, ts = 0.f;
#pragma unroll
                for (int j = 0; j < 8; j++) {
                    float c0 = acc[i][j][half * 2 + 0];
                    float c1 = acc[i][j][half * 2 + 1];
                    ss += c0 * aw[2 * j] + c1 * aw[2 * j + 1];
                    ts += c0 * bw[2 * j] + c1 * bw[2 * j + 1];
                }
                ss += __shfl_xor_sync(FULL, ss, 1);
                ss += __shfl_xor_sync(FULL, ss, 2);
                ts += __shfl_xor_sync(FULL, ts, 1);
                ts += __shfl_xor_sync(FULL, ts, 2);
                int row = bm + m0 + i * 16 + g + half * 8;
                if (t == 0 && row < M) {
                    sOut[row * 8 + hh] = ss;
                    tOut[row * 8 + hh] = ts;
                }
            }
        }
    }
}

// ---------------- CSR build (per type t) ----------------
__global__ void zero_cnt(int t) {
    int i = blockIdx.x * blockDim.x + threadIdx.x;
    if (i < NN) g_cntd[t][i] = 0;
}
__global__ void hist_kernel(const int* __restrict__ trg, int t) {
    int e = blockIdx.x * blockDim.x + threadIdx.x;
    if (e < EE) atomicAdd(&g_cntd[t][trg[e]], 1);
}
#define SCAN_CH 20
__global__ __launch_bounds__(1024) void scan_kernel(int t) {
    __shared__ int part[1024];
    int tid = threadIdx.x;
    int base = tid * SCAN_CH;
    int loc[SCAN_CH];
    int s = 0;
#pragma unroll
    for (int i = 0; i < SCAN_CH; i++) {
        int idx = base + i;
        int v = (idx < NN) ? g_cntd[t][idx] : 0;
        loc[i] = s;
        s += v;
    }
    part[tid] = s;
    __syncthreads();
    for (int d = 1; d < 1024; d <<= 1) {
        int v = (tid >= d) ? part[tid - d] : 0;
        __syncthreads();
        part[tid] += v;
        __syncthreads();
    }
    int excl = part[tid] - s;
#pragma unroll
    for (int i = 0; i < SCAN_CH; i++) {
        int idx = base + i;
        if (idx < NN) {
            int v = loc[i] + excl;
            g_rowptr[t][idx] = v;
            g_woffd[t][idx] = v;
        }
    }
    if (tid == 1023) g_rowptr[t][NN] = part[1023];
}
__global__ void fill_kernel(const int* __restrict__ src, const int* __restrict__ trg, int t) {
    int e = blockIdx.x * blockDim.x + threadIdx.x;
    if (e >= EE) return;
    int p = atomicAdd(&g_woffd[t][trg[e]], 1);
    g_csr[t][p] = src[e];
}

// ---------------- gather-aggregate: one warp per node, 4 edges per step ----------------
__global__ __launch_bounds__(256) void gather_agg(const int* __restrict__ csr,
                                                  const int* __restrict__ rowptr,
                                                  const uint32_t* __restrict__ hp,
                                                  const float* __restrict__ sArr,
                                                  const float* __restrict__ tArr,
                                                  void* __restrict__ outp,
                                                  int mode)
{
    const uint32_t FULL = 0xffffffffu;
    int node = (blockIdx.x * 256 + threadIdx.x) >> 5;
    int lane = threadIdx.x & 31;
    if (node >= NN) return;
    int beg = rowptr[node], end = rowptr[node + 1];

    const int h = lane & 7;
    const int eg = lane >> 3;
    float tval = tArr[node * 8 + h];

    float dsum = 0.f;
    float acc[2][8];
#pragma unroll
    for (int j = 0; j < 2; j++)
#pragma unroll
        for (int k = 0; k < 8; k++) acc[j][k] = 0.f;

    for (int base = beg; base < end; base += 32) {
        int nrem = end - base; if (nrem > 32) nrem = 32;
        int sv = (base + lane < end) ? csr[base + lane] : 0;

        for (int i4 = 0; i4 < nrem; i4 += 4) {
            int myEdge = i4 + eg;
            int srcE = __shfl_sync(FULL, sv, myEdge & 31);
            float ex = 0.f;
            if (myEdge < nrem) {
                float v = sArr[srcE * 8 + h] + tval;
                ex = __expf(fmaxf(v, 0.2f * v));   // global max-shift cancels in alpha
                dsum += ex;
            }
#pragma unroll
            for (int i = 0; i < 4; i++) {
                int srcp = __shfl_sync(FULL, sv, (i4 + i) & 31);
                const uint4* hv = (const uint4*)(hp + (size_t)srcp * 256);
#pragma unroll
                for (int j = 0; j < 2; j++) {
                    int c = lane + 32 * j;
                    float al = __shfl_sync(FULL, ex, (i << 3) | (c >> 3));
                    uint4 v = hv[c];
                    acc[j][0] += al * bf_lo(v.x); acc[j][1] += al * bf_hi(v.x);
                    acc[j][2] += al * bf_lo(v.y); acc[j][3] += al * bf_hi(v.y);
                    acc[j][4] += al * bf_lo(v.z); acc[j][5] += al * bf_hi(v.z);
                    acc[j][6] += al * bf_lo(v.w); acc[j][7] += al * bf_hi(v.w);
                }
            }
        }
    }

    dsum += __shfl_xor_sync(FULL, dsum, 8);
    dsum += __shfl_xor_sync(FULL, dsum, 16);

#pragma unroll
    for (int j = 0; j < 2; j++) {
        int c = lane + 32 * j;
        float dn = __shfl_sync(FULL, dsum, c >> 3) + 1e-16f;
        float inv = 1.f / dn;
        float v0 = acc[j][0] * inv, v1 = acc[j][1] * inv;
        float v2 = acc[j][2] * inv, v3 = acc[j][3] * inv;
        float v4 = acc[j][4] * inv, v5 = acc[j][5] * inv;
        float v6 = acc[j][6] * inv, v7 = acc[j][7] * inv;
        if (mode == 0) {
            float* out = (float*)outp;
            float4* ob = (float4*)(out + (size_t)node * 512 + c * 8);
            ob[0] = make_float4(v0, v1, v2, v3);
            ob[1] = make_float4(v4, v5, v6, v7);
        } else {
            uint32_t* out = (uint32_t*)outp;
            uint4 pk;
            pk.x = pack_bf16x2(eluf(v0), eluf(v1));
            pk.y = pack_bf16x2(eluf(v2), eluf(v3));
            pk.z = pack_bf16x2(eluf(v4), eluf(v5));
            pk.w = pack_bf16x2(eluf(v6), eluf(v7));
            ((uint4*)(out + (size_t)node * 256))[c] = pk;
        }
    }
}

// ---------------- prep kernels ----------------
__global__ void pack_bf16_k(uint32_t* __restrict__ dst, const float* __restrict__ src, int n2) {
    int i = blockIdx.x * blockDim.x + threadIdx.x;
    if (i < n2) dst[i] = pack_bf16x2(src[2 * i], src[2 * i + 1]);
}
__global__ void transpose_pack(uint32_t* __restrict__ Wt, const float* __restrict__ W) {
    int i = blockIdx.x * blockDim.x + threadIdx.x;
    if (i >= 256 * 64) return;
    int n = i >> 6, ku = i & 63;
    Wt[i] = pack_bf16x2(W[(2 * ku) * 256 + n], W[(2 * ku + 1) * 256 + n]);
}
__global__ void repack_pack(uint32_t* __restrict__ Bt, const float* __restrict__ w, int fin) {
    int finu = fin >> 1;
    int i = blockIdx.x * blockDim.x + threadIdx.x;
    if (i >= 512 * finu) return;
    int n = i / finu, ku = i % finu;
    int h = n >> 6, o = n & 63;
    int k0 = 2 * ku;
    Bt[i] = pack_bf16x2(w[((size_t)(h * fin + k0) << 6) + o],
                        w[((size_t)(h * fin + k0 + 1) << 6) + o]);
}

__global__ void fa_kernel(const uint32_t* __restrict__ trans1, const float* __restrict__ aw1) {
    int o = threadIdx.x;
    float acc = 0.f;
    for (int f2 = 0; f2 < 128; f2++) {
        uint32_t u = trans1[f2];
        acc += bf_lo(u) * aw1[(2 * f2) * 64 + o] + bf_hi(u) * aw1[(2 * f2 + 1) * 64 + o];
    }
    g_fa[o] = acc;
}

__global__ __launch_bounds__(64) void final_kernel(const float* __restrict__ aw2,
                                                   const float* __restrict__ am,
                                                   const float* __restrict__ fcw,
                                                   const float* __restrict__ fcb,
                                                   float* __restrict__ out) {
    __shared__ float ta[2][64];
    __shared__ float r0[64], r1[64];
    __shared__ float sc[2];
    int n = blockIdx.x, o = threadIdx.x;

    float m0 = 0.f, m1 = 0.f;
    const float* p0 = g_o1a + (size_t)n * 512 + o;
    const float* p1 = g_o1b + (size_t)n * 512 + o;
#pragma unroll
    for (int h = 0; h < 8; h++) { m0 += p0[h * 64]; m1 += p1[h * 64]; }
    m0 *= 0.125f; m1 *= 0.125f;
    ta[0][o] = m0; ta[1][o] = m1;
    __syncthreads();

    float amo = am[o];
    float fa = g_fa[o];
    {
        float acc0 = fa, acc1 = fa;
        for (int d = 0; d < 64; d++) {
            float w = aw2[d * 64 + o];
            acc0 += ta[0][d] * w;
            acc1 += ta[1][d] * w;
        }
        r0[o] = tanhf(acc0) * amo;
        r1[o] = tanhf(acc1) * amo;
    }
    __syncthreads();
    if (o == 0) {
        float s0 = 0.f, s1 = 0.f;
        for (int d = 0; d < 64; d++) { s0 += r0[d]; s1 += r1[d]; }
        sc[0] = s0; sc[1] = s1;
    }
    __syncthreads();
    float mx = fmaxf(sc[0], sc[1]);
    float b0 = __expf(sc[0] - mx), b1 = __expf(sc[1] - mx);
    float inv = 1.f / (b0 + b1);
    b0 *= inv; b1 *= inv;
    float fus = b0 * m0 + b1 * m1;

    r0[o] = m0 * fcw[o * 2 + 0] + m1 * fcw[(64 + o) * 2 + 0] + fus * fcw[(128 + o) * 2 + 0];
    r1[o] = m0 * fcw[o * 2 + 1] + m1 * fcw[(64 + o) * 2 + 1] + fus * fcw[(128 + o) * 2 + 1];
    __syncthreads();
    if (o == 0) {
        float l0 = fcb[0], l1 = fcb[1];
        for (int d = 0; d < 64; d++) { l0 += r0[d]; l1 += r1[d]; }
        float m = fmaxf(l0, l1);
        float lse = m + logf(__expf(l0 - m) + __expf(l1 - m));
        out[n * 2 + 0] = l0 - lse;
        out[n * 2 + 1] = l1 - lse;
    }
}

// ---------------- launcher: fork/join, all prep + CSR on side streams ----------------
extern "C" void kernel_launch(void* const* d_in, const int* in_sizes, int n_in,
                              void* d_out, int out_size)
{
    const float* hemb[2] = {(const float*)d_in[0], (const float*)d_in[1]};
    const float* W[2]    = {(const float*)d_in[2], (const float*)d_in[3]};
    const float* gw[2][2]    = {{(const float*)d_in[4],  (const float*)d_in[7]},
                                {(const float*)d_in[10], (const float*)d_in[13]}};
    const float* gasrc[2][2] = {{(const float*)d_in[5],  (const float*)d_in[8]},
                                {(const float*)d_in[11], (const float*)d_in[14]}};
    const float* gatrg[2][2] = {{(const float*)d_in[6],  (const float*)d_in[9]},
                                {(const float*)d_in[12], (const float*)d_in[15]}};
    const float* aw1 = (const float*)d_in[16];
    const float* aw2 = (const float*)d_in[17];
    const float* am  = (const float*)d_in[18];
    const float* fcw = (const float*)d_in[19];
    const float* fcb = (const float*)d_in[20];
    const int* edge[2] = {(const int*)d_in[21], (const int*)d_in[22]};

    uint32_t *trans[2], *BpT[2], *Bp0[2], *Bp1[2], *hp[2], *x0[2];
    float *o1[2], *sArr[2], *tArr[2];
    int *csr[2], *rowptr[2];
    {
        uint32_t* ub;
        cudaGetSymbolAddress((void**)&ub, g_trans); trans[0] = ub; trans[1] = ub + NN * FUNI / 2;
        cudaGetSymbolAddress((void**)&ub, g_BpT);   BpT[0] = ub;   BpT[1] = ub + 256 * 64;
        cudaGetSymbolAddress((void**)&ub, g_Bp0);   Bp0[0] = ub;   Bp0[1] = ub + 512 * 128;
        cudaGetSymbolAddress((void**)&ub, g_Bp1);   Bp1[0] = ub;   Bp1[1] = ub + 512 * 256;
        cudaGetSymbolAddress((void**)&ub, g_hpd);   hp[0] = ub;    hp[1] = ub + NN * HF / 2;
        cudaGetSymbolAddress((void**)&ub, g_x0d);   x0[0] = ub;    x0[1] = ub + NN * HF / 2;
        float* fb;
        cudaGetSymbolAddress((void**)&fb, g_o1a);   o1[0] = fb;
        cudaGetSymbolAddress((void**)&fb, g_o1b);   o1[1] = fb;
        cudaGetSymbolAddress((void**)&fb, g_sd);    sArr[0] = fb;  sArr[1] = fb + NN * HH;
        cudaGetSymbolAddress((void**)&fb, g_td);    tArr[0] = fb;  tArr[1] = fb + NN * HH;
        int* ib;
        cudaGetSymbolAddress((void**)&ib, g_csr);    csr[0] = ib;    csr[1] = ib + EE;
        cudaGetSymbolAddress((void**)&ib, g_rowptr); rowptr[0] = ib; rowptr[1] = ib + (NN + 1);
    }

    cudaFuncSetAttribute(gemm_bf16, cudaFuncAttributeMaxDynamicSharedMemorySize, SMEM_GEMM);

    const dim3 gridT(FUNI / 128, (NN + 127) / 128);
    const dim3 gridH(HF / 128,  (NN + 127) / 128);
    const int gatherBlocks = (NN * 32 + 255) / 256;

    cudaStream_t chain[2] = {(cudaStream_t)0, g_hx.s1};
    cudaStream_t sideS[2] = {g_hx.s2, g_hx.s3};
    cudaEvent_t  csrE[2]  = {g_hx.ec0, g_hx.ec1};
    cudaEvent_t  prepE[2] = {g_hx.ep0, g_hx.ep1};

    // fork from the capture stream
    cudaEventRecord(g_hx.e0, chain[0]);
    cudaStreamWaitEvent(chain[1], g_hx.e0, 0);
    cudaStreamWaitEvent(sideS[0], g_hx.e0, 0);
    cudaStreamWaitEvent(sideS[1], g_hx.e0, 0);

    // side streams: all input-only prep, then CSR build
    for (int t = 0; t < 2; t++) {
        cudaStream_t s = sideS[t];
        pack_bf16_k<<<(NN * 64 + 255) / 256, 256, 0, s>>>(hp[t], hemb[t], NN * 64);
        transpose_pack<<<(256 * 64 + 255) / 256, 256, 0, s>>>(BpT[t], W[t]);
        repack_pack<<<(512 * 128 + 255) / 256, 256, 0, s>>>(Bp0[t], gw[t][0], FUNI);
        repack_pack<<<(512 * 256 + 255) / 256, 256, 0, s>>>(Bp1[t], gw[t][1], HF);
        cudaEventRecord(prepE[t], s);

        const int* src = edge[t];
        const int* trg = edge[t] + EE;
        zero_cnt<<<(NN + 255) / 256, 256, 0, s>>>(t);
        hist_kernel<<<(EE + 255) / 256, 256, 0, s>>>(trg, t);
        scan_kernel<<<1, 1024, 0, s>>>(t);
        fill_kernel<<<(EE + 255) / 256, 256, 0, s>>>(src, trg, t);
        cudaEventRecord(csrE[t], s);
    }

    for (int t = 0; t < 2; t++) {
        cudaStream_t s = chain[t];
        cudaStreamWaitEvent(s, prepE[t], 0);

        // trans GEMM (no s/t epilogue)
        gemm_bf16<<<gridT, 256, SMEM_GEMM, s>>>(hp[t], BpT[t], trans[t], NN, 128, FUNI,
                                                nullptr, nullptr, nullptr, nullptr);
        if (t == 1)
            fa_kernel<<<1, 64, 0, s>>>(trans[1], aw1);   // only needs trans[1]

        // layer 0 GEMM with fused s/t
        gemm_bf16<<<gridH, 256, SMEM_GEMM, s>>>(trans[t], Bp0[t], hp[t], NN, FUNI, HF,
                                                gasrc[t][0], gatrg[t][0], sArr[t], tArr[t]);
        cudaStreamWaitEvent(s, csrE[t], 0);
        gather_agg<<<gatherBlocks, 256, 0, s>>>(csr[t], rowptr[t], hp[t], sArr[t], tArr[t], x0[t], 1);

        // layer 1 GEMM with fused s/t
        gemm_bf16<<<gridH, 256, SMEM_GEMM, s>>>(x0[t], Bp1[t], hp[t], NN, HF, HF,
                                                gasrc[t][1], gatrg[t][1], sArr[t], tArr[t]);
        gather_agg<<<gatherBlocks, 256, 0, s>>>(csr[t], rowptr[t], hp[t], sArr[t], tArr[t], o1[t], 0);
    }

    // join
    cudaEventRecord(g_hx.e1, chain[1]);
    cudaStreamWaitEvent(chain[0], g_hx.e1, 0);

    final_kernel<<<NN, 64, 0, chain[0]>>>(aw2, am, fcw, fcb, (float*)d_out);
}

// round 16
// speedup vs baseline: 2.7578x; 1.0620x over previous
#include <cuda_runtime.h>
#include <cstdint>
#include <cstddef>

#define NN   20000
#define EE   320000
#define HH   8
#define FUNI 256
#define FOUT 64
#define HF   512   // H*FOUT

// ---------------- scratch (device globals; no runtime allocation) ----------------
__device__ uint32_t g_embP[2][NN * 64];          // packed emb [N][64u] (128 bf16)
__device__ uint32_t g_Wpk[2][128 * 128];         // packed W [128][128u] (256 bf16)
__device__ uint32_t g_Wc[2][512 * 64];           // combined layer-0 weight [512][64u]
__device__ uint32_t g_Bp0[2][512 * 128];         // layer-0 weights [512][128u]
__device__ uint32_t g_Bp1[2][512 * 256];         // layer-1 weights [512][256u]
__device__ uint32_t g_hpd[2][NN * HF / 2];       // projected features (bf16)
__device__ uint32_t g_x0d[2][NN * HF / 2];       // layer-0 aggregated (bf16, ELU'd)
__device__ float g_mean[2][NN * FOUT];           // layer-1 head-mean output (fp32)
__device__ float g_sd[2][NN * HH];
__device__ float g_td[2][NN * HH];
__device__ float g_fa[FOUT];

// CSR scratch (per type)
__device__ int g_cntd[2][NN];
__device__ int g_rowptr[2][NN + 1];
__device__ int g_woffd[2][NN];
__device__ int g_csr[2][EE];

// ---------------- static stream/event context (created at load, NOT during capture) ----
struct HxCtx {
    cudaStream_t s1, s2, s3;        // s1: type-1 chain; s2/s3: per-type prep+CSR
    cudaEvent_t e0, e1, ec0, ec1, ep0, ep1;
    HxCtx() {
        cudaStreamCreateWithFlags(&s1, cudaStreamNonBlocking);
        cudaStreamCreateWithFlags(&s2, cudaStreamNonBlocking);
        cudaStreamCreateWithFlags(&s3, cudaStreamNonBlocking);
        cudaEventCreateWithFlags(&e0, cudaEventDisableTiming);
        cudaEventCreateWithFlags(&e1, cudaEventDisableTiming);
        cudaEventCreateWithFlags(&ec0, cudaEventDisableTiming);
        cudaEventCreateWithFlags(&ec1, cudaEventDisableTiming);
        cudaEventCreateWithFlags(&ep0, cudaEventDisableTiming);
        cudaEventCreateWithFlags(&ep1, cudaEventDisableTiming);
    }
};
static HxCtx g_hx;

// ---------------- helpers ----------------
__device__ __forceinline__ uint32_t smem_to_u32(const void* p) {
    uint32_t a;
    asm("{ .reg .u64 t; cvta.to.shared.u64 t, %1; cvt.u32.u64 %0, t; }" : "=r"(a) : "l"(p));
    return a;
}
__device__ __forceinline__ void cp16(uint32_t saddr, const void* g) {
    asm volatile("cp.async.cg.shared.global [%0], [%1], 16;" :: "r"(saddr), "l"(g));
}
__device__ __forceinline__ void sts_zero16(uint32_t saddr) {
    asm volatile("st.shared.v4.b32 [%0], {%1,%1,%1,%1};" :: "r"(saddr), "r"(0u));
}
#define CP_COMMIT() asm volatile("cp.async.commit_group;" ::: "memory")
#define CP_WAIT2()  asm volatile("cp.async.wait_group 2;" ::: "memory")

__device__ __forceinline__ uint32_t pack_bf16x2(float a, float b) {
    uint32_t r;
    asm("cvt.rn.bf16x2.f32 %0, %1, %2;" : "=r"(r) : "f"(b), "f"(a));
    return r;
}
__device__ __forceinline__ float bf_lo(uint32_t u) { return __uint_as_float(u << 16); }
__device__ __forceinline__ float bf_hi(uint32_t u) { return __uint_as_float(u & 0xffff0000u); }
__device__ __forceinline__ float eluf(float x) { return x > 0.f ? x : (__expf(x) - 1.f); }

__device__ __forceinline__ void mma_bf16(float* c, const uint32_t* a, const uint32_t* b) {
    asm volatile("mma.sync.aligned.m16n8k16.row.col.f32.bf16.bf16.f32 "
                 "{%0,%1,%2,%3}, {%4,%5,%6,%7}, {%8,%9}, {%0,%1,%2,%3};"
                 : "+f"(c[0]), "+f"(c[1]), "+f"(c[2]), "+f"(c[3])
                 : "r"(a[0]), "r"(a[1]), "r"(a[2]), "r"(a[3]), "r"(b[0]), "r"(b[1]));
}

// ---------------- bf16 mma GEMM + fused s/t epilogue ----------------
#define STAGES  3
#define STRIDEU 20
#define TILEU   (128 * STRIDEU)
#define STAGEU  (2 * TILEU)
#define SMEM_GEMM (STAGES * STAGEU * 4)    // 61440 bytes

__global__ __launch_bounds__(256, 2)
void gemm_bf16(const uint32_t* __restrict__ A, const uint32_t* __restrict__ Bt,
               uint32_t* __restrict__ C, int M, int K, int NC,
               const float* __restrict__ asrc, const float* __restrict__ atrg,
               float* __restrict__ sOut, float* __restrict__ tOut)
{
    const uint32_t FULL = 0xffffffffu;
    extern __shared__ uint32_t smu[];
    const int tid  = threadIdx.x;
    const int wid  = tid >> 5, lane = tid & 31;
    const int g    = lane >> 2, t = lane & 3;
    const int bm   = blockIdx.y << 7, bn = blockIdx.x << 7;
    const int m0   = (wid >> 1) * 32;
    const int n0   = (wid & 1) * 64;
    const int KU   = K >> 1;
    const int NCU  = NC >> 1;
    const int P    = K >> 5;

    const uint32_t sb = smem_to_u32(smu);
    const int lrow = tid >> 2;
    const int lc4  = tid & 3;

    float acc[2][8][4];
#pragma unroll
    for (int i = 0; i < 2; i++)
#pragma unroll
        for (int j = 0; j < 8; j++)
#pragma unroll
            for (int q = 0; q < 4; q++) acc[i][j][q] = 0.f;

#pragma unroll
    for (int s = 0; s < STAGES; s++) {
        uint32_t stb = sb + s * STAGEU * 4;
#pragma unroll
        for (int j = 0; j < 2; j++) {
            int row = lrow + j * 64;
            uint32_t sa = stb + (row * STRIDEU + lc4 * 4) * 4;
            int ar = bm + row;
            if (ar < M) cp16(sa, A + (size_t)ar * KU + s * 16 + lc4 * 4);
            else        sts_zero16(sa);
            uint32_t sbB = stb + TILEU * 4 + (row * STRIDEU + lc4 * 4) * 4;
            cp16(sbB, Bt + (size_t)(bn + row) * KU + s * 16 + lc4 * 4);
        }
        CP_COMMIT();
    }

    for (int p = 0; p < P; p++) {
        const int slot = p % STAGES;
        CP_WAIT2();
        __syncthreads();
        const uint32_t* As = smu + slot * STAGEU;
        const uint32_t* Bs = As + TILEU;

#pragma unroll
        for (int ks = 0; ks < 2; ks++) {
            uint32_t a[2][4], b[8][2];
#pragma unroll
            for (int i = 0; i < 2; i++) {
                int base = (m0 + i * 16 + g) * STRIDEU + ks * 8 + t;
                a[i][0] = As[base];
                a[i][1] = As[base + 8 * STRIDEU];
                a[i][2] = As[base + 4];
                a[i][3] = As[base + 8 * STRIDEU + 4];
            }
#pragma unroll
            for (int j = 0; j < 8; j++) {
                int bb = (n0 + j * 8 + g) * STRIDEU + ks * 8 + t;
                b[j][0] = Bs[bb];
                b[j][1] = Bs[bb + 4];
            }
#pragma unroll
            for (int i = 0; i < 2; i++)
#pragma unroll
                for (int j = 0; j < 8; j++)
                    mma_bf16(acc[i][j], a[i], b[j]);
        }
        __syncthreads();

        int np = p + STAGES;
        if (np < P) {
            uint32_t stb = sb + slot * STAGEU * 4;
#pragma unroll
            for (int j = 0; j < 2; j++) {
                int row = lrow + j * 64;
                uint32_t sa = stb + (row * STRIDEU + lc4 * 4) * 4;
                int ar = bm + row;
                if (ar < M) cp16(sa, A + (size_t)ar * KU + np * 16 + lc4 * 4);
                else        sts_zero16(sa);
                uint32_t sbB = stb + TILEU * 4 + (row * STRIDEU + lc4 * 4) * 4;
                cp16(sbB, Bt + (size_t)(bn + row) * KU + np * 16 + lc4 * 4);
            }
        }
        CP_COMMIT();
    }

    // ---- epilogue 1: store bf16x2 C ----
#pragma unroll
    for (int i = 0; i < 2; i++) {
        int r0 = bm + m0 + i * 16 + g;
#pragma unroll
        for (int j = 0; j < 8; j++) {
            int colu = ((bn + n0 + j * 8) >> 1) + t;
            if (r0 < M)
                C[(size_t)r0 * NCU + colu] = pack_bf16x2(acc[i][j][0], acc[i][j][1]);
            if (r0 + 8 < M)
                C[(size_t)(r0 + 8) * NCU + colu] = pack_bf16x2(acc[i][j][2], acc[i][j][3]);
        }
    }

    // ---- epilogue 2: fused s/t projection (warp's 64 cols = exactly one head) ----
    if (sOut != nullptr) {
        int hh = (bn + n0) >> 6;
        const float* av = asrc + hh * 64;
        const float* bv = atrg + hh * 64;
        float aw[16], bw[16];
#pragma unroll
        for (int j = 0; j < 8; j++) {
            int c0 = j * 8 + 2 * t;
            aw[2 * j] = av[c0];     aw[2 * j + 1] = av[c0 + 1];
            bw[2 * j] = bv[c0];     bw[2 * j + 1] = bv[c0 + 1];
        }
#pragma unroll
        for (int i = 0; i < 2; i++) {
#pragma unroll
            for (int half = 0; half < 2; half++) {
                float ss = 0.f, ts = 0.f;
#pragma unroll
                for (int j = 0; j < 8; j++) {
                    float c0 = acc[i][j][half * 2 + 0];
                    float c1 = acc[i][j][half * 2 + 1];
                    ss += c0 * aw[2 * j] + c1 * aw[2 * j + 1];
                    ts += c0 * bw[2 * j] + c1 * bw[2 * j + 1];
                }
                ss += __shfl_xor_sync(FULL, ss, 1);
                ss += __shfl_xor_sync(FULL, ss, 2);
                ts += __shfl_xor_sync(FULL, ts, 1);
                ts += __shfl_xor_sync(FULL, ts, 2);
                int row = bm + m0 + i * 16 + g + half * 8;
                if (t == 0 && row < M) {
                    sOut[row * 8 + hh] = ss;
                    tOut[row * 8 + hh] = ts;
                }
            }
        }
    }
}

// ---------------- CSR build (per type t) ----------------
__global__ void zero_cnt(int t) {
    int i = blockIdx.x * blockDim.x + threadIdx.x;
    if (i < NN) g_cntd[t][i] = 0;
}
__global__ void hist_kernel(const int* __restrict__ trg, int t) {
    int e = blockIdx.x * blockDim.x + threadIdx.x;
    if (e < EE) atomicAdd(&g_cntd[t][trg[e]], 1);
}
#define SCAN_CH 20
__global__ __launch_bounds__(1024) void scan_kernel(int t) {
    __shared__ int part[1024];
    int tid = threadIdx.x;
    int base = tid * SCAN_CH;
    int loc[SCAN_CH];
    int s = 0;
#pragma unroll
    for (int i = 0; i < SCAN_CH; i++) {
        int idx = base + i;
        int v = (idx < NN) ? g_cntd[t][idx] : 0;
        loc[i] = s;
        s += v;
    }
    part[tid] = s;
    __syncthreads();
    for (int d = 1; d < 1024; d <<= 1) {
        int v = (tid >= d) ? part[tid - d] : 0;
        __syncthreads();
        part[tid] += v;
        __syncthreads();
    }
    int excl = part[tid] - s;
#pragma unroll
    for (int i = 0; i < SCAN_CH; i++) {
        int idx = base + i;
        if (idx < NN) {
            int v = loc[i] + excl;
            g_rowptr[t][idx] = v;
            g_woffd[t][idx] = v;
        }
    }
    if (tid == 1023) g_rowptr[t][NN] = part[1023];
}
__global__ void fill_kernel(const int* __restrict__ src, const int* __restrict__ trg, int t) {
    int e = blockIdx.x * blockDim.x + threadIdx.x;
    if (e >= EE) return;
    int p = atomicAdd(&g_woffd[t][trg[e]], 1);
    g_csr[t][p] = src[e];
}

// ---------------- gather-aggregate: one warp per node, 4 edges per step ----------------
// mode 1: ELU + bf16-packed out [N][256u].  mode 2: head-mean fp32 out [N][64].
__global__ __launch_bounds__(256) void gather_agg(const int* __restrict__ csr,
                                                  const int* __restrict__ rowptr,
                                                  const uint32_t* __restrict__ hp,
                                                  const float* __restrict__ sArr,
                                                  const float* __restrict__ tArr,
                                                  void* __restrict__ outp,
                                                  int mode)
{
    const uint32_t FULL = 0xffffffffu;
    int node = (blockIdx.x * 256 + threadIdx.x) >> 5;
    int lane = threadIdx.x & 31;
    if (node >= NN) return;
    int beg = rowptr[node], end = rowptr[node + 1];

    const int h = lane & 7;
    const int eg = lane >> 3;
    float tval = tArr[node * 8 + h];

    float dsum = 0.f;
    float acc[2][8];
#pragma unroll
    for (int j = 0; j < 2; j++)
#pragma unroll
        for (int k = 0; k < 8; k++) acc[j][k] = 0.f;

    for (int base = beg; base < end; base += 32) {
        int nrem = end - base; if (nrem > 32) nrem = 32;
        int sv = (base + lane < end) ? csr[base + lane] : 0;

        for (int i4 = 0; i4 < nrem; i4 += 4) {
            int myEdge = i4 + eg;
            int srcE = __shfl_sync(FULL, sv, myEdge & 31);
            float ex = 0.f;
            if (myEdge < nrem) {
                float v = sArr[srcE * 8 + h] + tval;
                ex = __expf(fmaxf(v, 0.2f * v));   // global max-shift cancels in alpha
                dsum += ex;
            }
#pragma unroll
            for (int i = 0; i < 4; i++) {
                int srcp = __shfl_sync(FULL, sv, (i4 + i) & 31);
                const uint4* hv = (const uint4*)(hp + (size_t)srcp * 256);
#pragma unroll
                for (int j = 0; j < 2; j++) {
                    int c = lane + 32 * j;
                    float al = __shfl_sync(FULL, ex, (i << 3) | (c >> 3));
                    uint4 v = hv[c];
                    acc[j][0] += al * bf_lo(v.x); acc[j][1] += al * bf_hi(v.x);
                    acc[j][2] += al * bf_lo(v.y); acc[j][3] += al * bf_hi(v.y);
                    acc[j][4] += al * bf_lo(v.z); acc[j][5] += al * bf_hi(v.z);
                    acc[j][6] += al * bf_lo(v.w); acc[j][7] += al * bf_hi(v.w);
                }
            }
        }
    }

    // full per-head denominators: after xor-8/16, lane L holds dn for head L&7
    dsum += __shfl_xor_sync(FULL, dsum, 8);
    dsum += __shfl_xor_sync(FULL, dsum, 16);

    if (mode == 1) {
        uint32_t* out = (uint32_t*)outp;
#pragma unroll
        for (int j = 0; j < 2; j++) {
            int c = lane + 32 * j;
            float dn = __shfl_sync(FULL, dsum, c >> 3) + 1e-16f;
            float inv = 1.f / dn;
            uint4 pk;
            pk.x = pack_bf16x2(eluf(acc[j][0] * inv), eluf(acc[j][1] * inv));
            pk.y = pack_bf16x2(eluf(acc[j][2] * inv), eluf(acc[j][3] * inv));
            pk.z = pack_bf16x2(eluf(acc[j][4] * inv), eluf(acc[j][5] * inv));
            pk.w = pack_bf16x2(eluf(acc[j][6] * inv), eluf(acc[j][7] * inv));
            ((uint4*)(out + (size_t)node * 256))[c] = pk;
        }
    } else {
        // head-mean: normalize each half by its head's denom, then reduce over
        // the lane-group bits (lanes sharing lane&7 cover heads {g, g+4} x 4 groups)
        float inv0 = 1.f / (__shfl_sync(FULL, dsum, lane >> 3) + 1e-16f);        // head lane>>3
        float inv1 = 1.f / (__shfl_sync(FULL, dsum, 4 + (lane >> 3)) + 1e-16f);  // head 4+lane>>3
        float m[8];
#pragma unroll
        for (int k = 0; k < 8; k++) {
            m[k] = acc[0][k] * inv0 + acc[1][k] * inv1;
            m[k] += __shfl_xor_sync(FULL, m[k], 8);
            m[k] += __shfl_xor_sync(FULL, m[k], 16);
        }
        if (lane < 8) {
            float* out = (float*)outp + (size_t)node * 64 + lane * 8;
            ((float4*)out)[0] = make_float4(m[0] * 0.125f, m[1] * 0.125f, m[2] * 0.125f, m[3] * 0.125f);
            ((float4*)out)[1] = make_float4(m[4] * 0.125f, m[5] * 0.125f, m[6] * 0.125f, m[7] * 0.125f);
        }
    }
}

// ---------------- prep kernels ----------------
__global__ void pack_bf16_k(uint32_t* __restrict__ dst, const float* __restrict__ src, int n2) {
    int i = blockIdx.x * blockDim.x + threadIdx.x;
    if (i < n2) dst[i] = pack_bf16x2(src[2 * i], src[2 * i + 1]);
}
__global__ void repack_pack(uint32_t* __restrict__ Bt, const float* __restrict__ w, int fin) {
    int finu = fin >> 1;
    int i = blockIdx.x * blockDim.x + threadIdx.x;
    if (i >= 512 * finu) return;
    int n = i / finu, ku = i % finu;
    int h = n >> 6, o = n & 63;
    int k0 = 2 * ku;
    Bt[i] = pack_bf16x2(w[((size_t)(h * fin + k0) << 6) + o],
                        w[((size_t)(h * fin + k0 + 1) << 6) + o]);
}

// fa[o] = (hemb1[0,:] @ W1) @ aw1[:,o], all fp32 from raw inputs
__global__ __launch_bounds__(64) void fa_kernel(const float* __restrict__ hemb1,
                                                const float* __restrict__ W1,
                                                const float* __restrict__ aw1) {
    __shared__ float tr[256];
    int o = threadIdx.x;
    for (int f = o; f < 256; f += 64) {
        float a = 0.f;
        for (int k = 0; k < 128; k++) a += hemb1[k] * W1[k * 256 + f];
        tr[f] = a;
    }
    __syncthreads();
    float a = 0.f;
    for (int f = 0; f < 256; f++) a += tr[f] * aw1[f * 64 + o];
    g_fa[o] = a;
}

__global__ __launch_bounds__(64) void final_kernel(const float* __restrict__ aw2,
                                                   const float* __restrict__ am,
                                                   const float* __restrict__ fcw,
                                                   const float* __restrict__ fcb,
                                                   float* __restrict__ out) {
    __shared__ float ta[2][64];
    __shared__ float r0[64], r1[64];
    __shared__ float sc[2];
    int n = blockIdx.x, o = threadIdx.x;

    float m0 = g_mean[0][(size_t)n * 64 + o];
    float m1 = g_mean[1][(size_t)n * 64 + o];
    ta[0][o] = m0; ta[1][o] = m1;
    __syncthreads();

    float amo = am[o];
    float fa = g_fa[o];
    {
        float acc0 = fa, acc1 = fa;
        for (int d = 0; d < 64; d++) {
            float w = aw2[d * 64 + o];
            acc0 += ta[0][d] * w;
            acc1 += ta[1][d] * w;
        }
        r0[o] = tanhf(acc0) * amo;
        r1[o] = tanhf(acc1) * amo;
    }
    __syncthreads();
    if (o == 0) {
        float s0 = 0.f, s1 = 0.f;
        for (int d = 0; d < 64; d++) { s0 += r0[d]; s1 += r1[d]; }
        sc[0] = s0; sc[1] = s1;
    }
    __syncthreads();
    float mx = fmaxf(sc[0], sc[1]);
    float b0 = __expf(sc[0] - mx), b1 = __expf(sc[1] - mx);
    float inv = 1.f / (b0 + b1);
    b0 *= inv; b1 *= inv;
    float fus = b0 * m0 + b1 * m1;

    r0[o] = m0 * fcw[o * 2 + 0] + m1 * fcw[(64 + o) * 2 + 0] + fus * fcw[(128 + o) * 2 + 0];
    r1[o] = m0 * fcw[o * 2 + 1] + m1 * fcw[(64 + o) * 2 + 1] + fus * fcw[(128 + o) * 2 + 1];
    __syncthreads();
    if (o == 0) {
        float l0 = fcb[0], l1 = fcb[1];
        for (int d = 0; d < 64; d++) { l0 += r0[d]; l1 += r1[d]; }
        float m = fmaxf(l0, l1);
        float lse = m + logf(__expf(l0 - m) + __expf(l1 - m));
        out[n * 2 + 0] = l0 - lse;
        out[n * 2 + 1] = l1 - lse;
    }
}

// ---------------- launcher: fork/join, all prep + CSR + weight-combine on side streams ----
extern "C" void kernel_launch(void* const* d_in, const int* in_sizes, int n_in,
                              void* d_out, int out_size)
{
    const float* hemb[2] = {(const float*)d_in[0], (const float*)d_in[1]};
    const float* W[2]    = {(const float*)d_in[2], (const float*)d_in[3]};
    const float* gw[2][2]    = {{(const float*)d_in[4],  (const float*)d_in[7]},
                                {(const float*)d_in[10], (const float*)d_in[13]}};
    const float* gasrc[2][2] = {{(const float*)d_in[5],  (const float*)d_in[8]},
                                {(const float*)d_in[11], (const float*)d_in[14]}};
    const float* gatrg[2][2] = {{(const float*)d_in[6],  (const float*)d_in[9]},
                                {(const float*)d_in[12], (const float*)d_in[15]}};
    const float* aw1 = (const float*)d_in[16];
    const float* aw2 = (const float*)d_in[17];
    const float* am  = (const float*)d_in[18];
    const float* fcw = (const float*)d_in[19];
    const float* fcb = (const float*)d_in[20];
    const int* edge[2] = {(const int*)d_in[21], (const int*)d_in[22]};

    uint32_t *embP[2], *Wpk[2], *Wc[2], *Bp0[2], *Bp1[2], *hp[2], *x0[2];
    float *meanArr[2], *sArr[2], *tArr[2];
    int *csr[2], *rowptr[2];
    {
        uint32_t* ub;
        cudaGetSymbolAddress((void**)&ub, g_embP);  embP[0] = ub;  embP[1] = ub + NN * 64;
        cudaGetSymbolAddress((void**)&ub, g_Wpk);   Wpk[0] = ub;   Wpk[1] = ub + 128 * 128;
        cudaGetSymbolAddress((void**)&ub, g_Wc);    Wc[0] = ub;    Wc[1] = ub + 512 * 64;
        cudaGetSymbolAddress((void**)&ub, g_Bp0);   Bp0[0] = ub;   Bp0[1] = ub + 512 * 128;
        cudaGetSymbolAddress((void**)&ub, g_Bp1);   Bp1[0] = ub;   Bp1[1] = ub + 512 * 256;
        cudaGetSymbolAddress((void**)&ub, g_hpd);   hp[0] = ub;    hp[1] = ub + NN * HF / 2;
        cudaGetSymbolAddress((void**)&ub, g_x0d);   x0[0] = ub;    x0[1] = ub + NN * HF / 2;
        float* fb;
        cudaGetSymbolAddress((void**)&fb, g_mean);  meanArr[0] = fb; meanArr[1] = fb + NN * FOUT;
        cudaGetSymbolAddress((void**)&fb, g_sd);    sArr[0] = fb;  sArr[1] = fb + NN * HH;
        cudaGetSymbolAddress((void**)&fb, g_td);    tArr[0] = fb;  tArr[1] = fb + NN * HH;
        int* ib;
        cudaGetSymbolAddress((void**)&ib, g_csr);    csr[0] = ib;    csr[1] = ib + EE;
        cudaGetSymbolAddress((void**)&ib, g_rowptr); rowptr[0] = ib; rowptr[1] = ib + (NN + 1);
    }

    cudaFuncSetAttribute(gemm_bf16, cudaFuncAttributeMaxDynamicSharedMemorySize, SMEM_GEMM);

    const dim3 gridH(HF / 128,  (NN + 127) / 128);   // layer GEMMs over nodes
    const dim3 gridWc(1, 4);                          // 512x128 weight-combine GEMM
    const int gatherBlocks = (NN * 32 + 255) / 256;

    cudaStream_t chain[2] = {(cudaStream_t)0, g_hx.s1};
    cudaStream_t sideS[2] = {g_hx.s2, g_hx.s3};
    cudaEvent_t  csrE[2]  = {g_hx.ec0, g_hx.ec1};
    cudaEvent_t  prepE[2] = {g_hx.ep0, g_hx.ep1};

    // fork from the capture stream
    cudaEventRecord(g_hx.e0, chain[0]);
    cudaStreamWaitEvent(chain[1], g_hx.e0, 0);
    cudaStreamWaitEvent(sideS[0], g_hx.e0, 0);
    cudaStreamWaitEvent(sideS[1], g_hx.e0, 0);

    // side streams: prep + weight-combine + CSR build (+ fa for type 1)
    for (int t = 0; t < 2; t++) {
        cudaStream_t s = sideS[t];
        pack_bf16_k<<<(NN * 64 + 255) / 256, 256, 0, s>>>(embP[t], hemb[t], NN * 64);
        pack_bf16_k<<<(128 * 128 + 255) / 256, 256, 0, s>>>(Wpk[t], W[t], 128 * 128);
        repack_pack<<<(512 * 128 + 255) / 256, 256, 0, s>>>(Bp0[t], gw[t][0], FUNI);
        // Wc[n][f] = sum_k Bp0[n][k] * W[f][k]  (C = Bp0 @ Wpk^T), 512x128, K=256
        gemm_bf16<<<gridWc, 256, SMEM_GEMM, s>>>(Bp0[t], Wpk[t], Wc[t], 512, 256, 128,
                                                 nullptr, nullptr, nullptr, nullptr);
        repack_pack<<<(512 * 256 + 255) / 256, 256, 0, s>>>(Bp1[t], gw[t][1], HF);
        if (t == 1)
            fa_kernel<<<1, 64, 0, s>>>(hemb[1], W[1], aw1);
        cudaEventRecord(prepE[t], s);

        const int* src = edge[t];
        const int* trg = edge[t] + EE;
        zero_cnt<<<(NN + 255) / 256, 256, 0, s>>>(t);
        hist_kernel<<<(EE + 255) / 256, 256, 0, s>>>(trg, t);
        scan_kernel<<<1, 1024, 0, s>>>(t);
        fill_kernel<<<(EE + 255) / 256, 256, 0, s>>>(src, trg, t);
        cudaEventRecord(csrE[t], s);
    }

    for (int t = 0; t < 2; t++) {
        cudaStream_t s = chain[t];
        cudaStreamWaitEvent(s, prepE[t], 0);

        // layer 0: emb @ Wc (K=128), fused s/t
        gemm_bf16<<<gridH, 256, SMEM_GEMM, s>>>(embP[t], Wc[t], hp[t], NN, 128, HF,
                                                gasrc[t][0], gatrg[t][0], sArr[t], tArr[t]);
        cudaStreamWaitEvent(s, csrE[t], 0);
        gather_agg<<<gatherBlocks, 256, 0, s>>>(csr[t], rowptr[t], hp[t], sArr[t], tArr[t], x0[t], 1);

        // layer 1 (K=512), fused s/t; gather emits head-means
        gemm_bf16<<<gridH, 256, SMEM_GEMM, s>>>(x0[t], Bp1[t], hp[t], NN, HF, HF,
                                                gasrc[t][1], gatrg[t][1], sArr[t], tArr[t]);
        gather_agg<<<gatherBlocks, 256, 0, s>>>(csr[t], rowptr[t], hp[t], sArr[t], tArr[t], meanArr[t], 2);
    }

    // join
    cudaEventRecord(g_hx.e1, chain[1]);
    cudaStreamWaitEvent(chain[0], g_hx.e1, 0);

    final_kernel<<<NN, 64, 0, chain[0]>>>(aw2, am, fcw, fcb, (float*)d_out);
}